// round 6
// baseline (speedup 1.0000x reference)
#include <cuda_runtime.h>
#include <math.h>
#include <stdint.h>

#define BATCH 32
#define DEPTH 12
#define CDIM 768
#define NHEADS 12
#define HD 64
#define NTOK 197
#define NPATCH 196
#define GRD 14
#define PSZ 16
#define HIDDIM 3072
#define NCLS 1000
#define IMG 224
#define HALFW 3

#define NSM 148
#define PGRID (NSM * 2)   // persistent grid size

// ---------------- scratch (device globals; no allocation allowed) -------------
__device__ float g_xp[BATCH * NPATCH * CDIM];
__device__ float g_t[BATCH * NTOK * CDIM];
__device__ float g_h[BATCH * NTOK * CDIM];
__device__ float g_qkv[BATCH * NTOK * 3 * CDIM];
__device__ float g_o[BATCH * NTOK * CDIM];
__device__ float g_mlp[BATCH * NTOK * HIDDIM];
__device__ float g_cls[BATCH * CDIM];

// ================= TF32 tensor-core GEMM, persistent + cp.async pipeline =====
#define TCBM 128
#define TCBN 128
#define TCBK 16
#define ASTR (TCBK + 4)
#define BSTR (TCBN + 4)
#define NSTAGE 3

__device__ __forceinline__ uint32_t f2tf32(float x) {
    uint32_t r;
    asm("cvt.rna.tf32.f32 %0, %1;" : "=r"(r) : "f"(x));
    return r;
}

__device__ __forceinline__ void mma_tf32(float* d, const uint32_t* a, const uint32_t* b) {
    asm volatile(
        "mma.sync.aligned.m16n8k8.row.col.f32.tf32.tf32.f32 "
        "{%0,%1,%2,%3}, {%4,%5,%6,%7}, {%8,%9}, {%0,%1,%2,%3};"
        : "+f"(d[0]), "+f"(d[1]), "+f"(d[2]), "+f"(d[3])
        : "r"(a[0]), "r"(a[1]), "r"(a[2]), "r"(a[3]), "r"(b[0]), "r"(b[1]));
}

__device__ __forceinline__ void cp16(uint32_t dst_smem, const void* src, int size) {
    asm volatile("cp.async.cg.shared.global [%0], [%1], 16, %2;\n"
                 :: "r"(dst_smem), "l"(src), "r"(size));
}
__device__ __forceinline__ void cp_commit() {
    asm volatile("cp.async.commit_group;\n");
}
template <int NWAIT>
__device__ __forceinline__ void cp_wait() {
    asm volatile("cp.async.wait_group %0;\n" :: "n"(NWAIT));
}

template <bool BT, bool GELU>
__global__ void __launch_bounds__(256, 2)
gemm_tc(int M, int N, int K,
        const float* __restrict__ A, const float* __restrict__ B,
        const float* __restrict__ bias, const float* __restrict__ resid,
        float* __restrict__ C) {
    __shared__ uint32_t As[NSTAGE][TCBM][ASTR];
    __shared__ uint32_t Bs[NSTAGE][BT ? (TCBM * ASTR) : (TCBK * BSTR)];

    const int tid = threadIdx.x;
    const int lane = tid & 31;
    const int warp = tid >> 5;
    const int wm = (warp >> 2) * 64;
    const int wn = (warp & 3) * 32;
    const int r = lane >> 2;
    const int c = lane & 3;

    const int tiles_n = (N + TCBN - 1) / TCBN;
    const int tiles_m = (M + TCBM - 1) / TCBM;
    const int tiles = tiles_m * tiles_n;
    const int iters = K / TCBK;

    for (int tile = blockIdx.x; tile < tiles; tile += gridDim.x) {
        const int m0 = (tile / tiles_n) * TCBM;
        const int n0 = (tile % tiles_n) * TCBN;

        float acc[4][4][4];
#pragma unroll
        for (int mt = 0; mt < 4; mt++)
#pragma unroll
            for (int nt = 0; nt < 4; nt++)
#pragma unroll
                for (int i = 0; i < 4; i++) acc[mt][nt][i] = 0.f;

        auto load_stage = [&](int stage, int k0) {
#pragma unroll
            for (int j = 0; j < 2; j++) {
                int ci = tid + j * 256;
                int m = ci >> 2;
                int kc = (ci & 3) << 2;
                int gm = m0 + m;
                uint32_t dst = (uint32_t)__cvta_generic_to_shared(&As[stage][m][kc]);
                const float* src = &A[(size_t)gm * K + k0 + kc];
                cp16(dst, src, (gm < M) ? 16 : 0);
            }
            if (!BT) {
#pragma unroll
                for (int j = 0; j < 2; j++) {
                    int ci = tid + j * 256;
                    int k = ci >> 5;
                    int nc = (ci & 31) << 2;
                    uint32_t dst = (uint32_t)__cvta_generic_to_shared(&Bs[stage][k * BSTR + nc]);
                    const float* src = &B[(size_t)(k0 + k) * N + n0 + nc];
                    cp16(dst, src, 16);
                }
            } else {
#pragma unroll
                for (int j = 0; j < 2; j++) {
                    int ci = tid + j * 256;
                    int n = ci >> 2;
                    int kc = (ci & 3) << 2;
                    uint32_t dst = (uint32_t)__cvta_generic_to_shared(&Bs[stage][n * ASTR + kc]);
                    const float* src = &B[(size_t)(n0 + n) * K + k0 + kc];
                    cp16(dst, src, 16);
                }
            }
        };

        load_stage(0, 0);
        cp_commit();
        load_stage(1, TCBK);
        cp_commit();

        int buf = 0;
        for (int it = 0; it < iters; ++it) {
            cp_wait<1>();
            __syncthreads();

#pragma unroll
            for (int ks = 0; ks < TCBK; ks += 8) {
                uint32_t af[4][4], bf[4][2];
#pragma unroll
                for (int mt = 0; mt < 4; mt++) {
                    int mb = wm + mt * 16 + r;
                    af[mt][0] = f2tf32(__uint_as_float(As[buf][mb][ks + c]));
                    af[mt][1] = f2tf32(__uint_as_float(As[buf][mb + 8][ks + c]));
                    af[mt][2] = f2tf32(__uint_as_float(As[buf][mb][ks + c + 4]));
                    af[mt][3] = f2tf32(__uint_as_float(As[buf][mb + 8][ks + c + 4]));
                }
#pragma unroll
                for (int nt = 0; nt < 4; nt++) {
                    int nb = wn + nt * 8 + r;
                    if (!BT) {
                        bf[nt][0] = f2tf32(__uint_as_float(Bs[buf][(ks + c) * BSTR + nb]));
                        bf[nt][1] = f2tf32(__uint_as_float(Bs[buf][(ks + c + 4) * BSTR + nb]));
                    } else {
                        bf[nt][0] = f2tf32(__uint_as_float(Bs[buf][nb * ASTR + ks + c]));
                        bf[nt][1] = f2tf32(__uint_as_float(Bs[buf][nb * ASTR + ks + c + 4]));
                    }
                }
#pragma unroll
                for (int mt = 0; mt < 4; mt++)
#pragma unroll
                    for (int nt = 0; nt < 4; nt++)
                        mma_tf32(acc[mt][nt], af[mt], bf[nt]);
            }
            __syncthreads();

            if (it + 2 < iters) {
                int nb2 = buf + 2;
                if (nb2 >= NSTAGE) nb2 -= NSTAGE;
                load_stage(nb2, (it + 2) * TCBK);
            }
            cp_commit();

            buf = (buf == NSTAGE - 1) ? 0 : buf + 1;
        }

        // ---- epilogue ----
#pragma unroll
        for (int mt = 0; mt < 4; mt++) {
#pragma unroll
            for (int half = 0; half < 2; half++) {
                int gm = m0 + wm + mt * 16 + r + half * 8;
                if (gm >= M) continue;
#pragma unroll
                for (int nt = 0; nt < 4; nt++) {
                    int gn = n0 + wn + nt * 8 + c * 2;
                    float v0 = acc[mt][nt][half * 2 + 0];
                    float v1 = acc[mt][nt][half * 2 + 1];
                    if (bias) {
                        v0 += bias[gn];
                        v1 += bias[gn + 1];
                    }
                    if (GELU) {
                        v0 = 0.5f * v0 * (1.f + erff(v0 * 0.70710678118654752f));
                        v1 = 0.5f * v1 * (1.f + erff(v1 * 0.70710678118654752f));
                    }
                    if (resid) {
                        const float2 rr = *reinterpret_cast<const float2*>(
                            &resid[(size_t)gm * N + gn]);
                        v0 += rr.x;
                        v1 += rr.y;
                    }
                    *reinterpret_cast<float2*>(&C[(size_t)gm * N + gn]) =
                        make_float2(v0, v1);
                }
            }
        }
    }
}

// ---------------- small SIMT GEMM (head: M=32, N=1000) ------------------------
#define BM 128
#define BN 128
#define BK 8
#define TM 8
#define TN 8

__global__ void __launch_bounds__(256)
gemm_small(int M, int N, int K,
           const float* __restrict__ A, const float* __restrict__ B,
           const float* __restrict__ bias, float* __restrict__ C) {
    __shared__ float As[BK][BM];
    __shared__ float Bs[BK][BN];
    const int tid = threadIdx.x;
    const int m0 = blockIdx.y * BM;
    const int n0 = blockIdx.x * BN;
    const int tx = tid % (BN / TN);
    const int ty = tid / (BN / TN);

    float acc[TM][TN];
#pragma unroll
    for (int i = 0; i < TM; i++)
#pragma unroll
        for (int j = 0; j < TN; j++) acc[i][j] = 0.f;

    const int arow = tid / (BK / 4);
    const int acol = (tid % (BK / 4)) * 4;
    const int brow = tid / (BN / 4);
    const int bcol = (tid % (BN / 4)) * 4;

    for (int k0 = 0; k0 < K; k0 += BK) {
        {
            int gm = m0 + arow;
            float4 v = make_float4(0.f, 0.f, 0.f, 0.f);
            if (gm < M)
                v = *reinterpret_cast<const float4*>(&A[(size_t)gm * K + k0 + acol]);
            As[acol + 0][arow] = v.x;
            As[acol + 1][arow] = v.y;
            As[acol + 2][arow] = v.z;
            As[acol + 3][arow] = v.w;
        }
        {
            int gn = n0 + bcol;
            float t0 = (gn + 0 < N) ? B[(size_t)(k0 + brow) * N + gn + 0] : 0.f;
            float t1 = (gn + 1 < N) ? B[(size_t)(k0 + brow) * N + gn + 1] : 0.f;
            float t2 = (gn + 2 < N) ? B[(size_t)(k0 + brow) * N + gn + 2] : 0.f;
            float t3 = (gn + 3 < N) ? B[(size_t)(k0 + brow) * N + gn + 3] : 0.f;
            Bs[brow][bcol + 0] = t0;
            Bs[brow][bcol + 1] = t1;
            Bs[brow][bcol + 2] = t2;
            Bs[brow][bcol + 3] = t3;
        }
        __syncthreads();
#pragma unroll
        for (int kk = 0; kk < BK; kk++) {
            float ra[TM], rb[TN];
#pragma unroll
            for (int i = 0; i < TM; i++) ra[i] = As[kk][ty * TM + i];
#pragma unroll
            for (int j = 0; j < TN; j++) rb[j] = Bs[kk][tx * TN + j];
#pragma unroll
            for (int i = 0; i < TM; i++)
#pragma unroll
                for (int j = 0; j < TN; j++) acc[i][j] = fmaf(ra[i], rb[j], acc[i][j]);
        }
        __syncthreads();
    }
#pragma unroll
    for (int i = 0; i < TM; i++) {
        int gm = m0 + ty * TM + i;
        if (gm >= M) continue;
#pragma unroll
        for (int j = 0; j < TN; j++) {
            int gn = n0 + tx * TN + j;
            if (gn >= N) continue;
            float v = acc[i][j];
            if (bias) v += bias[gn];
            C[(size_t)gm * N + gn] = v;
        }
    }
}

// ---------------- patch gather -----------------------------------------------
__global__ void gather_kernel(const float* __restrict__ x) {
    int idx = blockIdx.x * blockDim.x + threadIdx.x;
    const int total = BATCH * NPATCH * CDIM;
    if (idx >= total) return;
    int k = idx % CDIM;
    int g = (idx / CDIM) % NPATCH;
    int b = idx / (CDIM * NPATCH);
    int ch = k / (PSZ * PSZ);
    int pr = (k / PSZ) % PSZ;
    int pc = k % PSZ;
    int gr = g / GRD;
    int gc = g % GRD;
    g_xp[idx] = x[(((size_t)b * 3 + ch) * IMG + gr * PSZ + pr) * IMG + gc * PSZ + pc];
}

// ---------------- assemble t = [cls; patches] + pos --------------------------
__global__ void assemble_kernel(const float* __restrict__ cls_tok,
                                const float* __restrict__ pos) {
    int idx = blockIdx.x * blockDim.x + threadIdx.x;
    const int total = BATCH * NTOK * CDIM;
    if (idx >= total) return;
    int c = idx % CDIM;
    int n = (idx / CDIM) % NTOK;
    int b = idx / (CDIM * NTOK);
    float v = (n == 0) ? cls_tok[c] : g_h[((size_t)b * NPATCH + n - 1) * CDIM + c];
    g_t[idx] = v + pos[(size_t)n * CDIM + c];
}

// ---------------- layernorm (warp-shuffle reduction) --------------------------
__global__ void __launch_bounds__(256)
ln_kernel(const float* __restrict__ x, long in_stride,
          const float* __restrict__ w, const float* __restrict__ b,
          float* __restrict__ y, long out_stride) {
    const float* row = x + (size_t)blockIdx.x * in_stride;
    float* out = y + (size_t)blockIdx.x * out_stride;
    int tid = threadIdx.x;
    float v0 = row[tid], v1 = row[tid + 256], v2 = row[tid + 512];
    float s = v0 + v1 + v2;
    float s2 = v0 * v0 + v1 * v1 + v2 * v2;
#pragma unroll
    for (int o = 16; o > 0; o >>= 1) {
        s += __shfl_xor_sync(0xffffffffu, s, o);
        s2 += __shfl_xor_sync(0xffffffffu, s2, o);
    }
    __shared__ float ps[8], ps2[8];
    if ((tid & 31) == 0) {
        ps[tid >> 5] = s;
        ps2[tid >> 5] = s2;
    }
    __syncthreads();
    float ts = ps[tid & 7], ts2 = ps2[tid & 7];
#pragma unroll
    for (int o = 4; o > 0; o >>= 1) {
        ts += __shfl_xor_sync(0xffffffffu, ts, o);
        ts2 += __shfl_xor_sync(0xffffffffu, ts2, o);
    }
    float mu = ts * (1.f / CDIM);
    float var = ts2 * (1.f / CDIM) - mu * mu;
    float rstd = rsqrtf(var + 1e-5f);
    out[tid] = (v0 - mu) * rstd * w[tid] + b[tid];
    out[tid + 256] = (v1 - mu) * rstd * w[tid + 256] + b[tid + 256];
    out[tid + 512] = (v2 - mu) * rstd * w[tid + 512] + b[tid + 512];
}

// ---------------- fused flash attention --------------------------------------
#define FBQ 32
#define FBK 32

__device__ __forceinline__ bool attn_allowed(int q, int k) {
    if (q == 0 || k == 0) return true;
    int qr = (q - 1) / GRD, qc = (q - 1) % GRD;
    int kr = (k - 1) / GRD, kc = (k - 1) % GRD;
    return (abs(qr - kr) <= HALFW) && (abs(qc - kc) <= HALFW);
}

__global__ void __launch_bounds__(256)
flash_kernel() {
    const int b = blockIdx.z;
    const int h = blockIdx.y;
    const int q0 = blockIdx.x * FBQ;
    const int tid = threadIdx.x;

    __shared__ float Qs[FBQ][HD + 1];
    __shared__ float Ks[FBK][HD + 1];
    __shared__ float Vs[FBK][HD + 1];
    __shared__ float Ps[FBQ][FBK + 1];

    const float* qkv = g_qkv;
    const size_t rowstride = 3 * CDIM;

    for (int idx = tid; idx < FBQ * HD; idx += 256) {
        int q = idx >> 6, d = idx & 63;
        int gq = q0 + q;
        Qs[q][d] = (gq < NTOK)
            ? qkv[((size_t)(b * NTOK + gq)) * rowstride + h * HD + d] : 0.f;
    }

    int klo = 0, khi = NTOK - 1;
    bool full = (q0 == 0);
    if (!full) {
        int qlo = q0, qhi = min(q0 + FBQ - 1, NTOK - 1);
        int qr_min = (qlo - 1) / GRD, qr_max = (qhi - 1) / GRD;
        klo = 1 + max(0, qr_min - HALFW) * GRD;
        khi = min(NTOK - 1, (qr_max + HALFW) * GRD + GRD);
    }

    const int q = tid >> 3;
    const int j = tid & 7;
    const int gq = q0 + q;
    const bool qvalid = (gq < NTOK);
    const int dbase = j * 8;

    float m_old = -INFINITY, l = 0.f;
    float acc[8];
#pragma unroll
    for (int i = 0; i < 8; i++) acc[i] = 0.f;

    for (int kt = 0; kt < (NTOK + FBK - 1) / FBK; kt++) {
        int kbase = kt * FBK;
        if (!(kt == 0 || full || (kbase + FBK - 1 >= klo && kbase <= khi)))
            continue;

        __syncthreads();
        for (int idx = tid; idx < FBK * HD; idx += 256) {
            int kk = idx >> 6, d = idx & 63;
            int gk = kbase + kk;
            if (gk < NTOK) {
                Ks[kk][d] = qkv[((size_t)(b * NTOK + gk)) * rowstride + CDIM + h * HD + d];
                Vs[kk][d] = qkv[((size_t)(b * NTOK + gk)) * rowstride + 2 * CDIM + h * HD + d];
            } else {
                Ks[kk][d] = 0.f;
                Vs[kk][d] = 0.f;
            }
        }
        __syncthreads();

        float s[4];
#pragma unroll
        for (int i = 0; i < 4; i++) {
            int kc = j + i * 8;
            float a = 0.f;
#pragma unroll
            for (int d = 0; d < HD; d++) a = fmaf(Qs[q][d], Ks[kc][d], a);
            a *= 0.125f;
            int gk = kbase + kc;
            if (!qvalid || gk >= NTOK || !attn_allowed(gq, gk)) a = -INFINITY;
            s[i] = a;
        }
        float mt = fmaxf(fmaxf(s[0], s[1]), fmaxf(s[2], s[3]));
#pragma unroll
        for (int o = 1; o < 8; o <<= 1)
            mt = fmaxf(mt, __shfl_xor_sync(0xffffffffu, mt, o));
        float m_new = fmaxf(m_old, mt);
        float scale = (m_new == -INFINITY) ? 1.f : __expf(m_old - m_new);
        float psum = 0.f;
#pragma unroll
        for (int i = 0; i < 4; i++) {
            float p = (s[i] == -INFINITY) ? 0.f : __expf(s[i] - m_new);
            Ps[q][j + i * 8] = p;
            psum += p;
        }
#pragma unroll
        for (int o = 1; o < 8; o <<= 1)
            psum += __shfl_xor_sync(0xffffffffu, psum, o);
        l = l * scale + psum;
        m_old = m_new;
        __syncwarp();

#pragma unroll
        for (int i = 0; i < 8; i++) acc[i] *= scale;
        for (int kk = 0; kk < FBK; kk++) {
            float p = Ps[q][kk];
#pragma unroll
            for (int i = 0; i < 8; i++)
                acc[i] = fmaf(p, Vs[kk][dbase + i], acc[i]);
        }
        __syncwarp();
    }

    if (qvalid) {
        float inv = 1.f / l;
#pragma unroll
        for (int i = 0; i < 8; i++)
            g_o[((size_t)(b * NTOK + gq)) * CDIM + h * HD + dbase + i] = acc[i] * inv;
    }
}

extern "C" void kernel_launch(void* const* d_in, const int* in_sizes, int n_in,
                              void* d_out, int out_size) {
    const float* x       = (const float*)d_in[0];
    const float* patch_w = (const float*)d_in[1];
    const float* patch_b = (const float*)d_in[2];
    const float* cls_tok = (const float*)d_in[3];
    const float* pos     = (const float*)d_in[4];
    const float* ln1_w   = (const float*)d_in[5];
    const float* ln1_b   = (const float*)d_in[6];
    const float* qkv_w   = (const float*)d_in[7];
    const float* proj_w  = (const float*)d_in[8];
    const float* proj_b  = (const float*)d_in[9];
    const float* ln2_w   = (const float*)d_in[10];
    const float* ln2_b   = (const float*)d_in[11];
    const float* mlp_w1  = (const float*)d_in[12];
    const float* mlp_b1  = (const float*)d_in[13];
    const float* mlp_w2  = (const float*)d_in[14];
    const float* mlp_b2  = (const float*)d_in[15];
    const float* norm_w  = (const float*)d_in[16];
    const float* norm_b  = (const float*)d_in[17];
    const float* head_w  = (const float*)d_in[18];
    const float* head_b  = (const float*)d_in[19];
    float* out = (float*)d_out;

    float *xp, *t, *h, *qkv, *o, *mlp, *cls;
    cudaGetSymbolAddress((void**)&xp, g_xp);
    cudaGetSymbolAddress((void**)&t, g_t);
    cudaGetSymbolAddress((void**)&h, g_h);
    cudaGetSymbolAddress((void**)&qkv, g_qkv);
    cudaGetSymbolAddress((void**)&o, g_o);
    cudaGetSymbolAddress((void**)&mlp, g_mlp);
    cudaGetSymbolAddress((void**)&cls, g_cls);

    const int Mtok = BATCH * NTOK;  // 6304

    // patch embed
    {
        int total = BATCH * NPATCH * CDIM;
        gather_kernel<<<(total + 255) / 256, 256>>>(x);
        gemm_tc<true, false><<<PGRID, 256>>>(
            BATCH * NPATCH, CDIM, CDIM, xp, patch_w, patch_b, nullptr, h);
        int tot2 = BATCH * NTOK * CDIM;
        assemble_kernel<<<(tot2 + 255) / 256, 256>>>(cls_tok, pos);
    }

    for (int i = 0; i < DEPTH; i++) {
        ln_kernel<<<Mtok, 256>>>(t, CDIM, ln1_w + i * CDIM, ln1_b + i * CDIM, h, CDIM);
        gemm_tc<false, false><<<PGRID, 256>>>(
            Mtok, 3 * CDIM, CDIM, h, qkv_w + (size_t)i * CDIM * 3 * CDIM,
            nullptr, nullptr, qkv);
        flash_kernel<<<dim3((NTOK + FBQ - 1) / FBQ, NHEADS, BATCH), 256>>>();
        gemm_tc<false, false><<<PGRID, 256>>>(
            Mtok, CDIM, CDIM, o, proj_w + (size_t)i * CDIM * CDIM,
            proj_b + i * CDIM, t, t);
        ln_kernel<<<Mtok, 256>>>(t, CDIM, ln2_w + i * CDIM, ln2_b + i * CDIM, h, CDIM);
        gemm_tc<false, true><<<PGRID, 256>>>(
            Mtok, HIDDIM, CDIM, h, mlp_w1 + (size_t)i * CDIM * HIDDIM,
            mlp_b1 + i * HIDDIM, nullptr, mlp);
        gemm_tc<false, false><<<PGRID, 256>>>(
            Mtok, CDIM, HIDDIM, mlp, mlp_w2 + (size_t)i * HIDDIM * CDIM,
            mlp_b2 + i * CDIM, t, t);
    }

    ln_kernel<<<BATCH, 256>>>(t, (long)NTOK * CDIM, norm_w, norm_b, cls, CDIM);
    gemm_small<<<dim3((NCLS + BN - 1) / BN, 1), 256>>>(
        BATCH, NCLS, CDIM, cls, head_w, head_b, out);
}

// round 8
// speedup vs baseline: 1.1129x; 1.1129x over previous
#include <cuda_runtime.h>
#include <math.h>
#include <stdint.h>

#define BATCH 32
#define DEPTH 12
#define CDIM 768
#define NHEADS 12
#define HD 64
#define NTOK 197
#define NPATCH 196
#define GRD 14
#define PSZ 16
#define HIDDIM 3072
#define NCLS 1000
#define IMG 224
#define HALFW 3

// ---------------- scratch (device globals; no allocation allowed) -------------
__device__ float g_xp[BATCH * NPATCH * CDIM];
__device__ float g_t[BATCH * NTOK * CDIM];
__device__ float g_h[BATCH * NTOK * CDIM];
__device__ float g_qkv[BATCH * NTOK * 3 * CDIM];
__device__ float g_o[BATCH * NTOK * CDIM];
__device__ float g_mlp[BATCH * NTOK * HIDDIM];
__device__ float g_cls[BATCH * CDIM];

// tf32-pre-rounded weights
#define W_PATCH_SZ (CDIM * 3 * PSZ * PSZ)                  // 589824
#define W_QKV_SZ   (DEPTH * CDIM * 3 * CDIM)               // 21233664
#define W_PROJ_SZ  (DEPTH * CDIM * CDIM)                   // 7077888
#define W_MLP1_SZ  (DEPTH * CDIM * HIDDIM)                 // 28311552
#define W_MLP2_SZ  (DEPTH * HIDDIM * CDIM)                 // 28311552
#define OFF_PATCH 0
#define OFF_QKV   (OFF_PATCH + W_PATCH_SZ)
#define OFF_PROJ  (OFF_QKV + W_QKV_SZ)
#define OFF_MLP1  (OFF_PROJ + W_PROJ_SZ)
#define OFF_MLP2  (OFF_MLP1 + W_MLP1_SZ)
#define W_TOTAL   (OFF_MLP2 + W_MLP2_SZ)
__device__ float g_wbuf[W_TOTAL];

__device__ __forceinline__ uint32_t f2tf32(float x) {
    uint32_t r;
    asm("cvt.rna.tf32.f32 %0, %1;" : "=r"(r) : "f"(x));
    return r;
}
__device__ __forceinline__ float tf32r(float x) {
    return __uint_as_float(f2tf32(x));
}

// ---------------- weight pre-round (float4) -----------------------------------
__global__ void round_kernel(const float* __restrict__ src, float* __restrict__ dst,
                             int n4) {
    int i = blockIdx.x * blockDim.x + threadIdx.x;
    if (i >= n4) return;
    float4 v = reinterpret_cast<const float4*>(src)[i];
    v.x = tf32r(v.x);
    v.y = tf32r(v.y);
    v.z = tf32r(v.z);
    v.w = tf32r(v.w);
    reinterpret_cast<float4*>(dst)[i] = v;
}

// ================= TF32 tensor-core GEMM, cp.async 3-stage pipeline ==========
// All operands pre-rounded to tf32 -> no cvt in the inner loop.
#define TCBM 128
#define TCBN 128
#define TCBK 16
#define ASTR (TCBK + 4)
#define BSTR (TCBN + 4)
#define NSTAGE 3

__device__ __forceinline__ void mma_tf32(float* d, const uint32_t* a, const uint32_t* b) {
    asm volatile(
        "mma.sync.aligned.m16n8k8.row.col.f32.tf32.tf32.f32 "
        "{%0,%1,%2,%3}, {%4,%5,%6,%7}, {%8,%9}, {%0,%1,%2,%3};"
        : "+f"(d[0]), "+f"(d[1]), "+f"(d[2]), "+f"(d[3])
        : "r"(a[0]), "r"(a[1]), "r"(a[2]), "r"(a[3]), "r"(b[0]), "r"(b[1]));
}

__device__ __forceinline__ void cp16(uint32_t dst_smem, const void* src, int size) {
    asm volatile("cp.async.cg.shared.global [%0], [%1], 16, %2;\n"
                 :: "r"(dst_smem), "l"(src), "r"(size));
}
__device__ __forceinline__ void cp_commit() {
    asm volatile("cp.async.commit_group;\n");
}
template <int NWAIT>
__device__ __forceinline__ void cp_wait() {
    asm volatile("cp.async.wait_group %0;\n" :: "n"(NWAIT));
}

template <bool BT, bool GELU>
__global__ void __launch_bounds__(256, 2)
gemm_tc(int M, int N, int K,
        const float* __restrict__ A, const float* __restrict__ B,
        const float* __restrict__ bias, const float* __restrict__ resid,
        float* __restrict__ C) {
    __shared__ uint32_t As[NSTAGE][TCBM][ASTR];
    __shared__ uint32_t Bs[NSTAGE][BT ? (TCBM * ASTR) : (TCBK * BSTR)];

    const int tid = threadIdx.x;
    const int lane = tid & 31;
    const int warp = tid >> 5;
    const int m0 = blockIdx.y * TCBM;
    const int n0 = blockIdx.x * TCBN;
    const int wm = (warp >> 2) * 64;
    const int wn = (warp & 3) * 32;
    const int r = lane >> 2;
    const int c = lane & 3;

    float acc[4][4][4];
#pragma unroll
    for (int mt = 0; mt < 4; mt++)
#pragma unroll
        for (int nt = 0; nt < 4; nt++)
#pragma unroll
            for (int i = 0; i < 4; i++) acc[mt][nt][i] = 0.f;

    const int iters = K / TCBK;

    auto load_stage = [&](int stage, int k0) {
#pragma unroll
        for (int j = 0; j < 2; j++) {
            int ci = tid + j * 256;
            int m = ci >> 2;
            int kc = (ci & 3) << 2;
            int gm = m0 + m;
            uint32_t dst = (uint32_t)__cvta_generic_to_shared(&As[stage][m][kc]);
            const float* src = &A[(size_t)gm * K + k0 + kc];
            cp16(dst, src, (gm < M) ? 16 : 0);
        }
        if (!BT) {
#pragma unroll
            for (int j = 0; j < 2; j++) {
                int ci = tid + j * 256;
                int k = ci >> 5;
                int nc = (ci & 31) << 2;
                uint32_t dst = (uint32_t)__cvta_generic_to_shared(&Bs[stage][k * BSTR + nc]);
                const float* src = &B[(size_t)(k0 + k) * N + n0 + nc];
                cp16(dst, src, 16);
            }
        } else {
#pragma unroll
            for (int j = 0; j < 2; j++) {
                int ci = tid + j * 256;
                int n = ci >> 2;
                int kc = (ci & 3) << 2;
                uint32_t dst = (uint32_t)__cvta_generic_to_shared(&Bs[stage][n * ASTR + kc]);
                const float* src = &B[(size_t)(n0 + n) * K + k0 + kc];
                cp16(dst, src, 16);
            }
        }
    };

    load_stage(0, 0);
    cp_commit();
    load_stage(1, TCBK);
    cp_commit();

    int buf = 0;
    for (int it = 0; it < iters; ++it) {
        cp_wait<1>();
        __syncthreads();

#pragma unroll
        for (int ks = 0; ks < TCBK; ks += 8) {
            uint32_t af[4][4], bf[4][2];
#pragma unroll
            for (int mt = 0; mt < 4; mt++) {
                int mb = wm + mt * 16 + r;
                af[mt][0] = As[buf][mb][ks + c];
                af[mt][1] = As[buf][mb + 8][ks + c];
                af[mt][2] = As[buf][mb][ks + c + 4];
                af[mt][3] = As[buf][mb + 8][ks + c + 4];
            }
#pragma unroll
            for (int nt = 0; nt < 4; nt++) {
                int nb = wn + nt * 8 + r;
                if (!BT) {
                    bf[nt][0] = Bs[buf][(ks + c) * BSTR + nb];
                    bf[nt][1] = Bs[buf][(ks + c + 4) * BSTR + nb];
                } else {
                    bf[nt][0] = Bs[buf][nb * ASTR + ks + c];
                    bf[nt][1] = Bs[buf][nb * ASTR + ks + c + 4];
                }
            }
#pragma unroll
            for (int mt = 0; mt < 4; mt++)
#pragma unroll
                for (int nt = 0; nt < 4; nt++)
                    mma_tf32(acc[mt][nt], af[mt], bf[nt]);
        }
        __syncthreads();

        if (it + 2 < iters) {
            int nb2 = buf + 2;
            if (nb2 >= NSTAGE) nb2 -= NSTAGE;
            load_stage(nb2, (it + 2) * TCBK);
        }
        cp_commit();

        buf = (buf == NSTAGE - 1) ? 0 : buf + 1;
    }

    // ---- epilogue ----
#pragma unroll
    for (int mt = 0; mt < 4; mt++) {
#pragma unroll
        for (int half = 0; half < 2; half++) {
            int gm = m0 + wm + mt * 16 + r + half * 8;
            if (gm >= M) continue;
#pragma unroll
            for (int nt = 0; nt < 4; nt++) {
                int gn = n0 + wn + nt * 8 + c * 2;
                float v0 = acc[mt][nt][half * 2 + 0];
                float v1 = acc[mt][nt][half * 2 + 1];
                if (bias) {
                    v0 += bias[gn];
                    v1 += bias[gn + 1];
                }
                if (GELU) {
                    // output feeds the next GEMM directly -> round to tf32 here
                    v0 = tf32r(0.5f * v0 * (1.f + erff(v0 * 0.70710678118654752f)));
                    v1 = tf32r(0.5f * v1 * (1.f + erff(v1 * 0.70710678118654752f)));
                }
                if (resid) {
                    const float2 rr = *reinterpret_cast<const float2*>(
                        &resid[(size_t)gm * N + gn]);
                    v0 += rr.x;
                    v1 += rr.y;
                }
                *reinterpret_cast<float2*>(&C[(size_t)gm * N + gn]) =
                    make_float2(v0, v1);
            }
        }
    }
}

// ---------------- small SIMT GEMM (head: M=32, N=1000) ------------------------
#define BM 128
#define BN 128
#define BK 8
#define TM 8
#define TN 8

__global__ void __launch_bounds__(256)
gemm_small(int M, int N, int K,
           const float* __restrict__ A, const float* __restrict__ B,
           const float* __restrict__ bias, float* __restrict__ C) {
    __shared__ float As[BK][BM];
    __shared__ float Bs[BK][BN];
    const int tid = threadIdx.x;
    const int m0 = blockIdx.y * BM;
    const int n0 = blockIdx.x * BN;
    const int tx = tid % (BN / TN);
    const int ty = tid / (BN / TN);

    float acc[TM][TN];
#pragma unroll
    for (int i = 0; i < TM; i++)
#pragma unroll
        for (int j = 0; j < TN; j++) acc[i][j] = 0.f;

    const int arow = tid / (BK / 4);
    const int acol = (tid % (BK / 4)) * 4;
    const int brow = tid / (BN / 4);
    const int bcol = (tid % (BN / 4)) * 4;

    for (int k0 = 0; k0 < K; k0 += BK) {
        {
            int gm = m0 + arow;
            float4 v = make_float4(0.f, 0.f, 0.f, 0.f);
            if (gm < M)
                v = *reinterpret_cast<const float4*>(&A[(size_t)gm * K + k0 + acol]);
            As[acol + 0][arow] = v.x;
            As[acol + 1][arow] = v.y;
            As[acol + 2][arow] = v.z;
            As[acol + 3][arow] = v.w;
        }
        {
            int gn = n0 + bcol;
            float t0 = (gn + 0 < N) ? B[(size_t)(k0 + brow) * N + gn + 0] : 0.f;
            float t1 = (gn + 1 < N) ? B[(size_t)(k0 + brow) * N + gn + 1] : 0.f;
            float t2 = (gn + 2 < N) ? B[(size_t)(k0 + brow) * N + gn + 2] : 0.f;
            float t3 = (gn + 3 < N) ? B[(size_t)(k0 + brow) * N + gn + 3] : 0.f;
            Bs[brow][bcol + 0] = t0;
            Bs[brow][bcol + 1] = t1;
            Bs[brow][bcol + 2] = t2;
            Bs[brow][bcol + 3] = t3;
        }
        __syncthreads();
#pragma unroll
        for (int kk = 0; kk < BK; kk++) {
            float ra[TM], rb[TN];
#pragma unroll
            for (int i = 0; i < TM; i++) ra[i] = As[kk][ty * TM + i];
#pragma unroll
            for (int j = 0; j < TN; j++) rb[j] = Bs[kk][tx * TN + j];
#pragma unroll
            for (int i = 0; i < TM; i++)
#pragma unroll
                for (int j = 0; j < TN; j++) acc[i][j] = fmaf(ra[i], rb[j], acc[i][j]);
        }
        __syncthreads();
    }
#pragma unroll
    for (int i = 0; i < TM; i++) {
        int gm = m0 + ty * TM + i;
        if (gm >= M) continue;
#pragma unroll
        for (int j = 0; j < TN; j++) {
            int gn = n0 + tx * TN + j;
            if (gn >= N) continue;
            float v = acc[i][j];
            if (bias) v += bias[gn];
            C[(size_t)gm * N + gn] = v;
        }
    }
}

// ---------------- patch gather (tf32-rounded output) --------------------------
__global__ void gather_kernel(const float* __restrict__ x) {
    int idx = blockIdx.x * blockDim.x + threadIdx.x;
    const int total = BATCH * NPATCH * CDIM;
    if (idx >= total) return;
    int k = idx % CDIM;
    int g = (idx / CDIM) % NPATCH;
    int b = idx / (CDIM * NPATCH);
    int ch = k / (PSZ * PSZ);
    int pr = (k / PSZ) % PSZ;
    int pc = k % PSZ;
    int gr = g / GRD;
    int gc = g % GRD;
    g_xp[idx] = tf32r(x[(((size_t)b * 3 + ch) * IMG + gr * PSZ + pr) * IMG + gc * PSZ + pc]);
}

// ---------------- assemble t = [cls; patches] + pos --------------------------
__global__ void assemble_kernel(const float* __restrict__ cls_tok,
                                const float* __restrict__ pos) {
    int idx = blockIdx.x * blockDim.x + threadIdx.x;
    const int total = BATCH * NTOK * CDIM;
    if (idx >= total) return;
    int c = idx % CDIM;
    int n = (idx / CDIM) % NTOK;
    int b = idx / (CDIM * NTOK);
    float v = (n == 0) ? cls_tok[c] : g_h[((size_t)b * NPATCH + n - 1) * CDIM + c];
    g_t[idx] = v + pos[(size_t)n * CDIM + c];
}

// ---------------- layernorm (warp-shuffle; optional tf32 rounding) ------------
__global__ void __launch_bounds__(256)
ln_kernel(const float* __restrict__ x, long in_stride,
          const float* __restrict__ w, const float* __restrict__ b,
          float* __restrict__ y, long out_stride, int do_round) {
    const float* row = x + (size_t)blockIdx.x * in_stride;
    float* out = y + (size_t)blockIdx.x * out_stride;
    int tid = threadIdx.x;
    float v0 = row[tid], v1 = row[tid + 256], v2 = row[tid + 512];
    float s = v0 + v1 + v2;
    float s2 = v0 * v0 + v1 * v1 + v2 * v2;
#pragma unroll
    for (int o = 16; o > 0; o >>= 1) {
        s += __shfl_xor_sync(0xffffffffu, s, o);
        s2 += __shfl_xor_sync(0xffffffffu, s2, o);
    }
    __shared__ float ps[8], ps2[8];
    if ((tid & 31) == 0) {
        ps[tid >> 5] = s;
        ps2[tid >> 5] = s2;
    }
    __syncthreads();
    float ts = ps[tid & 7], ts2 = ps2[tid & 7];
#pragma unroll
    for (int o = 4; o > 0; o >>= 1) {
        ts += __shfl_xor_sync(0xffffffffu, ts, o);
        ts2 += __shfl_xor_sync(0xffffffffu, ts2, o);
    }
    float mu = ts * (1.f / CDIM);
    float var = ts2 * (1.f / CDIM) - mu * mu;
    float rstd = rsqrtf(var + 1e-5f);
    float o0 = (v0 - mu) * rstd * w[tid] + b[tid];
    float o1 = (v1 - mu) * rstd * w[tid + 256] + b[tid + 256];
    float o2 = (v2 - mu) * rstd * w[tid + 512] + b[tid + 512];
    if (do_round) {
        o0 = tf32r(o0);
        o1 = tf32r(o1);
        o2 = tf32r(o2);
    }
    out[tid] = o0;
    out[tid + 256] = o1;
    out[tid + 512] = o2;
}

// ---------------- fused flash attention (tf32-rounded output) -----------------
#define FBQ 32
#define FBK 32

__device__ __forceinline__ bool attn_allowed(int q, int k) {
    if (q == 0 || k == 0) return true;
    int qr = (q - 1) / GRD, qc = (q - 1) % GRD;
    int kr = (k - 1) / GRD, kc = (k - 1) % GRD;
    return (abs(qr - kr) <= HALFW) && (abs(qc - kc) <= HALFW);
}

__global__ void __launch_bounds__(256)
flash_kernel() {
    const int b = blockIdx.z;
    const int h = blockIdx.y;
    const int q0 = blockIdx.x * FBQ;
    const int tid = threadIdx.x;

    __shared__ float Qs[FBQ][HD + 1];
    __shared__ float Ks[FBK][HD + 1];
    __shared__ float Vs[FBK][HD + 1];
    __shared__ float Ps[FBQ][FBK + 1];

    const float* qkv = g_qkv;
    const size_t rowstride = 3 * CDIM;

    for (int idx = tid; idx < FBQ * HD; idx += 256) {
        int q = idx >> 6, d = idx & 63;
        int gq = q0 + q;
        Qs[q][d] = (gq < NTOK)
            ? qkv[((size_t)(b * NTOK + gq)) * rowstride + h * HD + d] : 0.f;
    }

    int klo = 0, khi = NTOK - 1;
    bool full = (q0 == 0);
    if (!full) {
        int qlo = q0, qhi = min(q0 + FBQ - 1, NTOK - 1);
        int qr_min = (qlo - 1) / GRD, qr_max = (qhi - 1) / GRD;
        klo = 1 + max(0, qr_min - HALFW) * GRD;
        khi = min(NTOK - 1, (qr_max + HALFW) * GRD + GRD);
    }

    const int q = tid >> 3;
    const int j = tid & 7;
    const int gq = q0 + q;
    const bool qvalid = (gq < NTOK);
    const int dbase = j * 8;

    float m_old = -INFINITY, l = 0.f;
    float acc[8];
#pragma unroll
    for (int i = 0; i < 8; i++) acc[i] = 0.f;

    for (int kt = 0; kt < (NTOK + FBK - 1) / FBK; kt++) {
        int kbase = kt * FBK;
        if (!(kt == 0 || full || (kbase + FBK - 1 >= klo && kbase <= khi)))
            continue;

        __syncthreads();
        for (int idx = tid; idx < FBK * HD; idx += 256) {
            int kk = idx >> 6, d = idx & 63;
            int gk = kbase + kk;
            if (gk < NTOK) {
                Ks[kk][d] = qkv[((size_t)(b * NTOK + gk)) * rowstride + CDIM + h * HD + d];
                Vs[kk][d] = qkv[((size_t)(b * NTOK + gk)) * rowstride + 2 * CDIM + h * HD + d];
            } else {
                Ks[kk][d] = 0.f;
                Vs[kk][d] = 0.f;
            }
        }
        __syncthreads();

        float s[4];
#pragma unroll
        for (int i = 0; i < 4; i++) {
            int kc = j + i * 8;
            float a = 0.f;
#pragma unroll
            for (int d = 0; d < HD; d++) a = fmaf(Qs[q][d], Ks[kc][d], a);
            a *= 0.125f;
            int gk = kbase + kc;
            if (!qvalid || gk >= NTOK || !attn_allowed(gq, gk)) a = -INFINITY;
            s[i] = a;
        }
        float mt = fmaxf(fmaxf(s[0], s[1]), fmaxf(s[2], s[3]));
#pragma unroll
        for (int o = 1; o < 8; o <<= 1)
            mt = fmaxf(mt, __shfl_xor_sync(0xffffffffu, mt, o));
        float m_new = fmaxf(m_old, mt);
        float scale = (m_new == -INFINITY) ? 1.f : __expf(m_old - m_new);
        float psum = 0.f;
#pragma unroll
        for (int i = 0; i < 4; i++) {
            float p = (s[i] == -INFINITY) ? 0.f : __expf(s[i] - m_new);
            Ps[q][j + i * 8] = p;
            psum += p;
        }
#pragma unroll
        for (int o = 1; o < 8; o <<= 1)
            psum += __shfl_xor_sync(0xffffffffu, psum, o);
        l = l * scale + psum;
        m_old = m_new;
        __syncwarp();

#pragma unroll
        for (int i = 0; i < 8; i++) acc[i] *= scale;
        for (int kk = 0; kk < FBK; kk++) {
            float p = Ps[q][kk];
#pragma unroll
            for (int i = 0; i < 8; i++)
                acc[i] = fmaf(p, Vs[kk][dbase + i], acc[i]);
        }
        __syncwarp();
    }

    if (qvalid) {
        float inv = 1.f / l;
#pragma unroll
        for (int i = 0; i < 8; i++)
            g_o[((size_t)(b * NTOK + gq)) * CDIM + h * HD + dbase + i] =
                tf32r(acc[i] * inv);
    }
}

// ---------------- launch helpers ---------------------------------------------
static inline dim3 tc_grid(int M, int N) {
    return dim3((N + TCBN - 1) / TCBN, (M + TCBM - 1) / TCBM);
}

extern "C" void kernel_launch(void* const* d_in, const int* in_sizes, int n_in,
                              void* d_out, int out_size) {
    const float* x       = (const float*)d_in[0];
    const float* patch_w = (const float*)d_in[1];
    const float* patch_b = (const float*)d_in[2];
    const float* cls_tok = (const float*)d_in[3];
    const float* pos     = (const float*)d_in[4];
    const float* ln1_w   = (const float*)d_in[5];
    const float* ln1_b   = (const float*)d_in[6];
    const float* qkv_w   = (const float*)d_in[7];
    const float* proj_w  = (const float*)d_in[8];
    const float* proj_b  = (const float*)d_in[9];
    const float* ln2_w   = (const float*)d_in[10];
    const float* ln2_b   = (const float*)d_in[11];
    const float* mlp_w1  = (const float*)d_in[12];
    const float* mlp_b1  = (const float*)d_in[13];
    const float* mlp_w2  = (const float*)d_in[14];
    const float* mlp_b2  = (const float*)d_in[15];
    const float* norm_w  = (const float*)d_in[16];
    const float* norm_b  = (const float*)d_in[17];
    const float* head_w  = (const float*)d_in[18];
    const float* head_b  = (const float*)d_in[19];
    float* out = (float*)d_out;

    float *xp, *t, *h, *qkv, *o, *mlp, *cls, *wbuf;
    cudaGetSymbolAddress((void**)&xp, g_xp);
    cudaGetSymbolAddress((void**)&t, g_t);
    cudaGetSymbolAddress((void**)&h, g_h);
    cudaGetSymbolAddress((void**)&qkv, g_qkv);
    cudaGetSymbolAddress((void**)&o, g_o);
    cudaGetSymbolAddress((void**)&mlp, g_mlp);
    cudaGetSymbolAddress((void**)&cls, g_cls);
    cudaGetSymbolAddress((void**)&wbuf, g_wbuf);

    const float* w_patch = wbuf + OFF_PATCH;
    const float* w_qkv   = wbuf + OFF_QKV;
    const float* w_proj  = wbuf + OFF_PROJ;
    const float* w_mlp1  = wbuf + OFF_MLP1;
    const float* w_mlp2  = wbuf + OFF_MLP2;

    // ---- pre-round all weights to tf32 (once per call) ----
    round_kernel<<<(W_PATCH_SZ / 4 + 255) / 256, 256>>>(patch_w, wbuf + OFF_PATCH, W_PATCH_SZ / 4);
    round_kernel<<<(W_QKV_SZ / 4 + 255) / 256, 256>>>(qkv_w, wbuf + OFF_QKV, W_QKV_SZ / 4);
    round_kernel<<<(W_PROJ_SZ / 4 + 255) / 256, 256>>>(proj_w, wbuf + OFF_PROJ, W_PROJ_SZ / 4);
    round_kernel<<<(W_MLP1_SZ / 4 + 255) / 256, 256>>>(mlp_w1, wbuf + OFF_MLP1, W_MLP1_SZ / 4);
    round_kernel<<<(W_MLP2_SZ / 4 + 255) / 256, 256>>>(mlp_w2, wbuf + OFF_MLP2, W_MLP2_SZ / 4);

    const int Mtok = BATCH * NTOK;  // 6304

    // patch embed
    {
        int total = BATCH * NPATCH * CDIM;
        gather_kernel<<<(total + 255) / 256, 256>>>(x);
        gemm_tc<true, false><<<tc_grid(BATCH * NPATCH, CDIM), 256>>>(
            BATCH * NPATCH, CDIM, CDIM, xp, w_patch, patch_b, nullptr, h);
        int tot2 = BATCH * NTOK * CDIM;
        assemble_kernel<<<(tot2 + 255) / 256, 256>>>(cls_tok, pos);
    }

    for (int i = 0; i < DEPTH; i++) {
        ln_kernel<<<Mtok, 256>>>(t, CDIM, ln1_w + i * CDIM, ln1_b + i * CDIM, h, CDIM, 1);
        gemm_tc<false, false><<<tc_grid(Mtok, 3 * CDIM), 256>>>(
            Mtok, 3 * CDIM, CDIM, h, w_qkv + (size_t)i * CDIM * 3 * CDIM,
            nullptr, nullptr, qkv);
        flash_kernel<<<dim3((NTOK + FBQ - 1) / FBQ, NHEADS, BATCH), 256>>>();
        gemm_tc<false, false><<<tc_grid(Mtok, CDIM), 256>>>(
            Mtok, CDIM, CDIM, o, w_proj + (size_t)i * CDIM * CDIM,
            proj_b + i * CDIM, t, t);
        ln_kernel<<<Mtok, 256>>>(t, CDIM, ln2_w + i * CDIM, ln2_b + i * CDIM, h, CDIM, 1);
        gemm_tc<false, true><<<tc_grid(Mtok, HIDDIM), 256>>>(
            Mtok, HIDDIM, CDIM, h, w_mlp1 + (size_t)i * CDIM * HIDDIM,
            mlp_b1 + i * HIDDIM, nullptr, mlp);
        gemm_tc<false, false><<<tc_grid(Mtok, CDIM), 256>>>(
            Mtok, CDIM, HIDDIM, mlp, w_mlp2 + (size_t)i * HIDDIM * CDIM,
            mlp_b2 + i * CDIM, t, t);
    }

    ln_kernel<<<BATCH, 256>>>(t, (long)NTOK * CDIM, norm_w, norm_b, cls, CDIM, 0);
    gemm_small<<<dim3((NCLS + BN - 1) / BN, 1), 256>>>(
        BATCH, NCLS, CDIM, cls, head_w, head_b, out);
}

// round 11
// speedup vs baseline: 1.5659x; 1.4070x over previous
#include <cuda_runtime.h>
#include <cuda_fp16.h>
#include <math.h>
#include <stdint.h>

#define BATCH 32
#define DEPTH 12
#define CDIM 768
#define NHEADS 12
#define HD 64
#define NTOK 197
#define NPATCH 196
#define GRD 14
#define PSZ 16
#define HIDDIM 3072
#define NCLS 1000
#define IMG 224
#define HALFW 3

// ---------------- scratch (device globals; no allocation allowed) -------------
__device__ __half g_xp16[BATCH * NPATCH * CDIM];
__device__ __half g_h16[BATCH * NTOK * CDIM];
__device__ __half g_o16[BATCH * NTOK * CDIM];
__device__ __half g_mlp16[BATCH * NTOK * HIDDIM];
__device__ float g_t[BATCH * NTOK * CDIM];
__device__ float g_h[BATCH * NTOK * CDIM];
__device__ float g_qkv[BATCH * NTOK * 3 * CDIM];
__device__ float g_cls[BATCH * CDIM];

// weights: (N,K) layout, fp16
#define W_PATCH_SZ (CDIM * 3 * PSZ * PSZ)
#define W_QKV_SZ   (DEPTH * CDIM * 3 * CDIM)
#define W_PROJ_SZ  (DEPTH * CDIM * CDIM)
#define W_MLP1_SZ  (DEPTH * CDIM * HIDDIM)
#define W_MLP2_SZ  (DEPTH * HIDDIM * CDIM)
#define OFF_PATCH 0
#define OFF_QKV   (OFF_PATCH + W_PATCH_SZ)
#define OFF_PROJ  (OFF_QKV + W_QKV_SZ)
#define OFF_MLP1  (OFF_PROJ + W_PROJ_SZ)
#define OFF_MLP2  (OFF_MLP1 + W_MLP1_SZ)
#define W_TOTAL   (OFF_MLP2 + W_MLP2_SZ)
__device__ __half g_w16[W_TOTAL];

// ---------------- helpers ------------------------------------------------------
__device__ __forceinline__ uint32_t smem_u32(const void* p) {
    uint32_t a;
    asm("{ .reg .u64 t; cvta.to.shared.u64 t, %1; cvt.u32.u64 %0, t; }"
        : "=r"(a) : "l"(p));
    return a;
}
__device__ __forceinline__ void cp16(uint32_t dst_smem, const void* src, int size) {
    asm volatile("cp.async.cg.shared.global [%0], [%1], 16, %2;\n"
                 :: "r"(dst_smem), "l"(src), "r"(size));
}
__device__ __forceinline__ void cp_commit() {
    asm volatile("cp.async.commit_group;\n");
}
template <int NWAIT>
__device__ __forceinline__ void cp_wait() {
    asm volatile("cp.async.wait_group %0;\n" :: "n"(NWAIT));
}

__device__ __forceinline__ void mma_f16(float* d, const uint32_t* a, const uint32_t* b) {
    asm volatile(
        "mma.sync.aligned.m16n8k16.row.col.f32.f16.f16.f32 "
        "{%0,%1,%2,%3}, {%4,%5,%6,%7}, {%8,%9}, {%0,%1,%2,%3};"
        : "+f"(d[0]), "+f"(d[1]), "+f"(d[2]), "+f"(d[3])
        : "r"(a[0]), "r"(a[1]), "r"(a[2]), "r"(a[3]), "r"(b[0]), "r"(b[1]));
}

// ================= FP16 tensor-core GEMM, cp.async 3-stage ====================
// C(MxN) = A(MxK) @ Bw(N,K)^T, A/Bw fp16, accumulate fp32.
// Block 128x128, 8 warps (warp tile 64x32 = 4x4 m16n8k16 frags), K slab 32.
#define GM 128
#define GN 128
#define GKH 32
#define ROWB 80                 // padded smem row: 64B data + 16B pad
#define ROWH 40                 // row stride in halves
#define TILEB (GM * ROWB)       // 10240
#define STAGEB (2 * TILEB)      // 20480
#define NST 3
#define GSMEM (NST * STAGEB)    // 61440

template <bool GELU, bool OUTH>
__global__ void __launch_bounds__(256, 2)
gemm_h(int M, int N, int K,
       const __half* __restrict__ A, const __half* __restrict__ Bw,
       const float* __restrict__ bias, const float* __restrict__ resid,
       void* __restrict__ Cout) {
    extern __shared__ char dsm[];
    const uint32_t sb = smem_u32(dsm);
    const int tid = threadIdx.x;
    const int lane = tid & 31;
    const int warp = tid >> 5;
    const int m0 = blockIdx.y * GM;
    const int n0 = blockIdx.x * GN;
    const int wm = (warp >> 2) * 64;
    const int wn = (warp & 3) * 32;
    const int r = lane >> 2;
    const int c = lane & 3;

    float acc[4][4][4];
#pragma unroll
    for (int mt = 0; mt < 4; mt++)
#pragma unroll
        for (int nt = 0; nt < 4; nt++)
#pragma unroll
            for (int i = 0; i < 4; i++) acc[mt][nt][i] = 0.f;

    const int iters = K / GKH;

    auto load_stage = [&](int s, int k0) {
        const uint32_t aB = sb + s * STAGEB;
        const uint32_t bB = aB + TILEB;
#pragma unroll
        for (int j = 0; j < 2; j++) {
            int ci = tid + j * 256;
            int row = ci >> 2, ch = ci & 3;
            int gm = m0 + row;
            cp16(aB + row * ROWB + ch * 16,
                 &A[(size_t)gm * K + k0 + ch * 8], (gm < M) ? 16 : 0);
            cp16(bB + row * ROWB + ch * 16,
                 &Bw[(size_t)(n0 + row) * K + k0 + ch * 8], 16);
        }
    };

    load_stage(0, 0);
    cp_commit();
    load_stage(1, GKH);
    cp_commit();

    int buf = 0;
    for (int it = 0; it < iters; ++it) {
        cp_wait<1>();
        __syncthreads();

        const __half* As = (const __half*)(dsm + buf * STAGEB);
        const __half* Bs = (const __half*)(dsm + buf * STAGEB + TILEB);

#pragma unroll
        for (int ks = 0; ks < GKH; ks += 16) {
            uint32_t af[4][4], bf[4][2];
#pragma unroll
            for (int mt = 0; mt < 4; mt++) {
                int mb = wm + mt * 16 + r;
                af[mt][0] = *(const uint32_t*)(As + mb * ROWH + ks + c * 2);
                af[mt][1] = *(const uint32_t*)(As + (mb + 8) * ROWH + ks + c * 2);
                af[mt][2] = *(const uint32_t*)(As + mb * ROWH + ks + c * 2 + 8);
                af[mt][3] = *(const uint32_t*)(As + (mb + 8) * ROWH + ks + c * 2 + 8);
            }
#pragma unroll
            for (int nt = 0; nt < 4; nt++) {
                int nb = wn + nt * 8 + r;
                bf[nt][0] = *(const uint32_t*)(Bs + nb * ROWH + ks + c * 2);
                bf[nt][1] = *(const uint32_t*)(Bs + nb * ROWH + ks + c * 2 + 8);
            }
#pragma unroll
            for (int mt = 0; mt < 4; mt++)
#pragma unroll
                for (int nt = 0; nt < 4; nt++)
                    mma_f16(acc[mt][nt], af[mt], bf[nt]);
        }
        __syncthreads();

        if (it + 2 < iters) {
            int nb2 = buf + 2;
            if (nb2 >= NST) nb2 -= NST;
            load_stage(nb2, (it + 2) * GKH);
        }
        cp_commit();

        buf = (buf == NST - 1) ? 0 : buf + 1;
    }

    // ---- epilogue ----
#pragma unroll
    for (int mt = 0; mt < 4; mt++) {
#pragma unroll
        for (int half = 0; half < 2; half++) {
            int gm = m0 + wm + mt * 16 + r + half * 8;
            if (gm >= M) continue;
#pragma unroll
            for (int nt = 0; nt < 4; nt++) {
                int gn = n0 + wn + nt * 8 + c * 2;
                float v0 = acc[mt][nt][half * 2 + 0];
                float v1 = acc[mt][nt][half * 2 + 1];
                if (bias) {
                    v0 += bias[gn];
                    v1 += bias[gn + 1];
                }
                if (GELU) {
                    v0 = 0.5f * v0 * (1.f + erff(v0 * 0.70710678118654752f));
                    v1 = 0.5f * v1 * (1.f + erff(v1 * 0.70710678118654752f));
                }
                if (resid) {
                    const float2 rr = *reinterpret_cast<const float2*>(
                        &resid[(size_t)gm * N + gn]);
                    v0 += rr.x;
                    v1 += rr.y;
                }
                if (OUTH) {
                    __half2 hv = __floats2half2_rn(v0, v1);
                    *reinterpret_cast<__half2*>(
                        (__half*)Cout + (size_t)gm * N + gn) = hv;
                } else {
                    *reinterpret_cast<float2*>(
                        (float*)Cout + (size_t)gm * N + gn) = make_float2(v0, v1);
                }
            }
        }
    }
}

// ---------------- weight preprocessing ----------------------------------------
// convert-only: src already (N,K) fp32 -> fp16
__global__ void half_kernel(const float* __restrict__ src, __half* __restrict__ dst,
                            int n4) {
    int i = blockIdx.x * blockDim.x + threadIdx.x;
    if (i >= n4) return;
    float4 v = reinterpret_cast<const float4*>(src)[i];
    __half2 h0 = __floats2half2_rn(v.x, v.y);
    __half2 h1 = __floats2half2_rn(v.z, v.w);
    reinterpret_cast<__half2*>(dst)[2 * i + 0] = h0;
    reinterpret_cast<__half2*>(dst)[2 * i + 1] = h1;
}

// (K,N) fp32 row-major -> (N,K) fp16 row-major; layer via blockIdx.z
__global__ void __launch_bounds__(256)
transpose_half_kernel(const float* __restrict__ src, __half* __restrict__ dst,
                      int K, int N) {
    __shared__ float tile[32][33];
    const float* s = src + (size_t)blockIdx.z * K * N;
    __half* d = dst + (size_t)blockIdx.z * K * N;
    int kb = blockIdx.y * 32, nb = blockIdx.x * 32;
    int tx = threadIdx.x & 31, ty = threadIdx.x >> 5;
#pragma unroll
    for (int r = 0; r < 32; r += 8)
        tile[ty + r][tx] = s[(size_t)(kb + ty + r) * N + nb + tx];
    __syncthreads();
#pragma unroll
    for (int r = 0; r < 32; r += 8)
        d[(size_t)(nb + ty + r) * K + kb + tx] = __float2half(tile[tx][ty + r]);
}

// ---------------- small SIMT GEMM (head: M=32, N=1000) ------------------------
#define BN 128

__global__ void __launch_bounds__(256)
gemm_small(int M, int N, int K,
           const float* __restrict__ A, const float* __restrict__ B,
           const float* __restrict__ bias, float* __restrict__ C) {
    __shared__ float As[8][128];
    __shared__ float Bs[8][132];
    const int tid = threadIdx.x;
    const int m0 = blockIdx.y * 128;
    const int n0 = blockIdx.x * BN;
    const int tx = tid % 16;
    const int ty = tid / 16;

    float acc[8][8];
#pragma unroll
    for (int i = 0; i < 8; i++)
#pragma unroll
        for (int j = 0; j < 8; j++) acc[i][j] = 0.f;

    const int arow = tid / 2;
    const int acol = (tid % 2) * 4;
    const int brow = tid / 32;
    const int bcol = (tid % 32) * 4;

    for (int k0 = 0; k0 < K; k0 += 8) {
        {
            int gm = m0 + arow;
            float4 v = make_float4(0.f, 0.f, 0.f, 0.f);
            if (gm < M)
                v = *reinterpret_cast<const float4*>(&A[(size_t)gm * K + k0 + acol]);
            As[acol + 0][arow] = v.x;
            As[acol + 1][arow] = v.y;
            As[acol + 2][arow] = v.z;
            As[acol + 3][arow] = v.w;
        }
        {
            int gn = n0 + bcol;
            Bs[brow][bcol + 0] = (gn + 0 < N) ? B[(size_t)(k0 + brow) * N + gn + 0] : 0.f;
            Bs[brow][bcol + 1] = (gn + 1 < N) ? B[(size_t)(k0 + brow) * N + gn + 1] : 0.f;
            Bs[brow][bcol + 2] = (gn + 2 < N) ? B[(size_t)(k0 + brow) * N + gn + 2] : 0.f;
            Bs[brow][bcol + 3] = (gn + 3 < N) ? B[(size_t)(k0 + brow) * N + gn + 3] : 0.f;
        }
        __syncthreads();
#pragma unroll
        for (int kk = 0; kk < 8; kk++) {
            float ra[8], rb[8];
#pragma unroll
            for (int i = 0; i < 8; i++) ra[i] = As[kk][ty * 8 + i];
#pragma unroll
            for (int j = 0; j < 8; j++) rb[j] = Bs[kk][tx * 8 + j];
#pragma unroll
            for (int i = 0; i < 8; i++)
#pragma unroll
                for (int j = 0; j < 8; j++) acc[i][j] = fmaf(ra[i], rb[j], acc[i][j]);
        }
        __syncthreads();
    }
#pragma unroll
    for (int i = 0; i < 8; i++) {
        int gm = m0 + ty * 8 + i;
        if (gm >= M) continue;
#pragma unroll
        for (int j = 0; j < 8; j++) {
            int gn = n0 + tx * 8 + j;
            if (gn >= N) continue;
            float v = acc[i][j];
            if (bias) v += bias[gn];
            C[(size_t)gm * N + gn] = v;
        }
    }
}

// ---------------- patch gather (fp16 output) ----------------------------------
__global__ void gather_kernel(const float* __restrict__ x) {
    int idx = blockIdx.x * blockDim.x + threadIdx.x;
    const int total = BATCH * NPATCH * CDIM;
    if (idx >= total) return;
    int k = idx % CDIM;
    int g = (idx / CDIM) % NPATCH;
    int b = idx / (CDIM * NPATCH);
    int ch = k / (PSZ * PSZ);
    int pr = (k / PSZ) % PSZ;
    int pc = k % PSZ;
    int gr = g / GRD;
    int gc = g % GRD;
    g_xp16[idx] = __float2half(
        x[(((size_t)b * 3 + ch) * IMG + gr * PSZ + pr) * IMG + gc * PSZ + pc]);
}

// ---------------- assemble t = [cls; patches] + pos --------------------------
__global__ void assemble_kernel(const float* __restrict__ cls_tok,
                                const float* __restrict__ pos) {
    int idx = blockIdx.x * blockDim.x + threadIdx.x;
    const int total = BATCH * NTOK * CDIM;
    if (idx >= total) return;
    int c = idx % CDIM;
    int n = (idx / CDIM) % NTOK;
    int b = idx / (CDIM * NTOK);
    float v = (n == 0) ? cls_tok[c] : g_h[((size_t)b * NPATCH + n - 1) * CDIM + c];
    g_t[idx] = v + pos[(size_t)n * CDIM + c];
}

// ---------------- layernorm (warp-shuffle; half or float out) -----------------
__global__ void __launch_bounds__(256)
ln_kernel(const float* __restrict__ x, long in_stride,
          const float* __restrict__ w, const float* __restrict__ b,
          void* __restrict__ y, long out_stride, int half_out) {
    const float* row = x + (size_t)blockIdx.x * in_stride;
    int tid = threadIdx.x;
    float v0 = row[tid], v1 = row[tid + 256], v2 = row[tid + 512];
    float s = v0 + v1 + v2;
    float s2 = v0 * v0 + v1 * v1 + v2 * v2;
#pragma unroll
    for (int o = 16; o > 0; o >>= 1) {
        s += __shfl_xor_sync(0xffffffffu, s, o);
        s2 += __shfl_xor_sync(0xffffffffu, s2, o);
    }
    __shared__ float ps[8], ps2[8];
    if ((tid & 31) == 0) {
        ps[tid >> 5] = s;
        ps2[tid >> 5] = s2;
    }
    __syncthreads();
    float ts = ps[tid & 7], ts2 = ps2[tid & 7];
#pragma unroll
    for (int o = 4; o > 0; o >>= 1) {
        ts += __shfl_xor_sync(0xffffffffu, ts, o);
        ts2 += __shfl_xor_sync(0xffffffffu, ts2, o);
    }
    float mu = ts * (1.f / CDIM);
    float var = ts2 * (1.f / CDIM) - mu * mu;
    float rstd = rsqrtf(var + 1e-5f);
    float o0 = (v0 - mu) * rstd * w[tid] + b[tid];
    float o1 = (v1 - mu) * rstd * w[tid + 256] + b[tid + 256];
    float o2 = (v2 - mu) * rstd * w[tid + 512] + b[tid + 512];
    if (half_out) {
        __half* out = (__half*)y + (size_t)blockIdx.x * out_stride;
        out[tid] = __float2half(o0);
        out[tid + 256] = __float2half(o1);
        out[tid + 512] = __float2half(o2);
    } else {
        float* out = (float*)y + (size_t)blockIdx.x * out_stride;
        out[tid] = o0;
        out[tid + 256] = o1;
        out[tid + 512] = o2;
    }
}

// ---------------- fused flash attention (fp16 output) -------------------------
#define FBQ 32
#define FBK 32

__device__ __forceinline__ bool attn_allowed(int q, int k) {
    if (q == 0 || k == 0) return true;
    int qr = (q - 1) / GRD, qc = (q - 1) % GRD;
    int kr = (k - 1) / GRD, kc = (k - 1) % GRD;
    return (abs(qr - kr) <= HALFW) && (abs(qc - kc) <= HALFW);
}

__global__ void __launch_bounds__(256)
flash_kernel() {
    const int b = blockIdx.z;
    const int h = blockIdx.y;
    const int q0 = blockIdx.x * FBQ;
    const int tid = threadIdx.x;

    __shared__ float Qs[FBQ][HD + 1];
    __shared__ float Ks[FBK][HD + 1];
    __shared__ float Vs[FBK][HD + 1];
    __shared__ float Ps[FBQ][FBK + 1];

    const float* qkv = g_qkv;
    const size_t rowstride = 3 * CDIM;

    for (int idx = tid; idx < FBQ * HD; idx += 256) {
        int q = idx >> 6, d = idx & 63;
        int gq = q0 + q;
        Qs[q][d] = (gq < NTOK)
            ? qkv[((size_t)(b * NTOK + gq)) * rowstride + h * HD + d] : 0.f;
    }

    int klo = 0, khi = NTOK - 1;
    bool full = (q0 == 0);
    if (!full) {
        int qlo = q0, qhi = min(q0 + FBQ - 1, NTOK - 1);
        int qr_min = (qlo - 1) / GRD, qr_max = (qhi - 1) / GRD;
        klo = 1 + max(0, qr_min - HALFW) * GRD;
        khi = min(NTOK - 1, (qr_max + HALFW) * GRD + GRD);
    }

    const int q = tid >> 3;
    const int j = tid & 7;
    const int gq = q0 + q;
    const bool qvalid = (gq < NTOK);
    const int dbase = j * 8;

    float m_old = -INFINITY, l = 0.f;
    float acc[8];
#pragma unroll
    for (int i = 0; i < 8; i++) acc[i] = 0.f;

    for (int kt = 0; kt < (NTOK + FBK - 1) / FBK; kt++) {
        int kbase = kt * FBK;
        if (!(kt == 0 || full || (kbase + FBK - 1 >= klo && kbase <= khi)))
            continue;

        __syncthreads();
        for (int idx = tid; idx < FBK * HD; idx += 256) {
            int kk = idx >> 6, d = idx & 63;
            int gk = kbase + kk;
            if (gk < NTOK) {
                Ks[kk][d] = qkv[((size_t)(b * NTOK + gk)) * rowstride + CDIM + h * HD + d];
                Vs[kk][d] = qkv[((size_t)(b * NTOK + gk)) * rowstride + 2 * CDIM + h * HD + d];
            } else {
                Ks[kk][d] = 0.f;
                Vs[kk][d] = 0.f;
            }
        }
        __syncthreads();

        float s[4];
#pragma unroll
        for (int i = 0; i < 4; i++) {
            int kc = j + i * 8;
            float a = 0.f;
#pragma unroll
            for (int d = 0; d < HD; d++) a = fmaf(Qs[q][d], Ks[kc][d], a);
            a *= 0.125f;
            int gk = kbase + kc;
            if (!qvalid || gk >= NTOK || !attn_allowed(gq, gk)) a = -INFINITY;
            s[i] = a;
        }
        float mt = fmaxf(fmaxf(s[0], s[1]), fmaxf(s[2], s[3]));
#pragma unroll
        for (int o = 1; o < 8; o <<= 1)
            mt = fmaxf(mt, __shfl_xor_sync(0xffffffffu, mt, o));
        float m_new = fmaxf(m_old, mt);
        float scale = (m_new == -INFINITY) ? 1.f : __expf(m_old - m_new);
        float psum = 0.f;
#pragma unroll
        for (int i = 0; i < 4; i++) {
            float p = (s[i] == -INFINITY) ? 0.f : __expf(s[i] - m_new);
            Ps[q][j + i * 8] = p;
            psum += p;
        }
#pragma unroll
        for (int o = 1; o < 8; o <<= 1)
            psum += __shfl_xor_sync(0xffffffffu, psum, o);
        l = l * scale + psum;
        m_old = m_new;
        __syncwarp();

#pragma unroll
        for (int i = 0; i < 8; i++) acc[i] *= scale;
        for (int kk = 0; kk < FBK; kk++) {
            float p = Ps[q][kk];
#pragma unroll
            for (int i = 0; i < 8; i++)
                acc[i] = fmaf(p, Vs[kk][dbase + i], acc[i]);
        }
        __syncwarp();
    }

    if (qvalid) {
        float inv = 1.f / l;
#pragma unroll
        for (int i = 0; i < 8; i++)
            g_o16[((size_t)(b * NTOK + gq)) * CDIM + h * HD + dbase + i] =
                __float2half(acc[i] * inv);
    }
}

// ---------------- launch helpers ---------------------------------------------
static inline dim3 gh_grid(int M, int N) {
    return dim3(N / GN, (M + GM - 1) / GM);
}

extern "C" void kernel_launch(void* const* d_in, const int* in_sizes, int n_in,
                              void* d_out, int out_size) {
    const float* x       = (const float*)d_in[0];
    const float* patch_w = (const float*)d_in[1];
    const float* patch_b = (const float*)d_in[2];
    const float* cls_tok = (const float*)d_in[3];
    const float* pos     = (const float*)d_in[4];
    const float* ln1_w   = (const float*)d_in[5];
    const float* ln1_b   = (const float*)d_in[6];
    const float* qkv_w   = (const float*)d_in[7];
    const float* proj_w  = (const float*)d_in[8];
    const float* proj_b  = (const float*)d_in[9];
    const float* ln2_w   = (const float*)d_in[10];
    const float* ln2_b   = (const float*)d_in[11];
    const float* mlp_w1  = (const float*)d_in[12];
    const float* mlp_b1  = (const float*)d_in[13];
    const float* mlp_w2  = (const float*)d_in[14];
    const float* mlp_b2  = (const float*)d_in[15];
    const float* norm_w  = (const float*)d_in[16];
    const float* norm_b  = (const float*)d_in[17];
    const float* head_w  = (const float*)d_in[18];
    const float* head_b  = (const float*)d_in[19];
    float* out = (float*)d_out;

    float *t, *h, *qkv, *cls;
    __half *xp16, *h16, *o16, *mlp16, *w16;
    cudaGetSymbolAddress((void**)&t, g_t);
    cudaGetSymbolAddress((void**)&h, g_h);
    cudaGetSymbolAddress((void**)&qkv, g_qkv);
    cudaGetSymbolAddress((void**)&cls, g_cls);
    cudaGetSymbolAddress((void**)&xp16, g_xp16);
    cudaGetSymbolAddress((void**)&h16, g_h16);
    cudaGetSymbolAddress((void**)&o16, g_o16);
    cudaGetSymbolAddress((void**)&mlp16, g_mlp16);
    cudaGetSymbolAddress((void**)&w16, g_w16);

    cudaFuncSetAttribute(gemm_h<false, false>,
                         cudaFuncAttributeMaxDynamicSharedMemorySize, GSMEM);
    cudaFuncSetAttribute(gemm_h<true, true>,
                         cudaFuncAttributeMaxDynamicSharedMemorySize, GSMEM);

    const __half* w_patch = w16 + OFF_PATCH;
    const __half* w_qkv   = w16 + OFF_QKV;
    const __half* w_proj  = w16 + OFF_PROJ;
    const __half* w_mlp1  = w16 + OFF_MLP1;
    const __half* w_mlp2  = w16 + OFF_MLP2;

    // ---- preprocess weights: (N,K) fp16 ----
    half_kernel<<<(W_PATCH_SZ / 4 + 255) / 256, 256>>>(
        patch_w, w16 + OFF_PATCH, W_PATCH_SZ / 4);  // already (N,K)
    transpose_half_kernel<<<dim3(3 * CDIM / 32, CDIM / 32, DEPTH), 256>>>(
        qkv_w, w16 + OFF_QKV, CDIM, 3 * CDIM);
    transpose_half_kernel<<<dim3(CDIM / 32, CDIM / 32, DEPTH), 256>>>(
        proj_w, w16 + OFF_PROJ, CDIM, CDIM);
    transpose_half_kernel<<<dim3(HIDDIM / 32, CDIM / 32, DEPTH), 256>>>(
        mlp_w1, w16 + OFF_MLP1, CDIM, HIDDIM);
    transpose_half_kernel<<<dim3(CDIM / 32, HIDDIM / 32, DEPTH), 256>>>(
        mlp_w2, w16 + OFF_MLP2, HIDDIM, CDIM);

    const int Mtok = BATCH * NTOK;  // 6304

    // patch embed
    {
        int total = BATCH * NPATCH * CDIM;
        gather_kernel<<<(total + 255) / 256, 256>>>(x);
        gemm_h<false, false><<<gh_grid(BATCH * NPATCH, CDIM), 256, GSMEM>>>(
            BATCH * NPATCH, CDIM, CDIM, xp16, w_patch, patch_b, nullptr, h);
        int tot2 = BATCH * NTOK * CDIM;
        assemble_kernel<<<(tot2 + 255) / 256, 256>>>(cls_tok, pos);
    }

    for (int i = 0; i < DEPTH; i++) {
        ln_kernel<<<Mtok, 256>>>(t, CDIM, ln1_w + i * CDIM, ln1_b + i * CDIM,
                                 h16, CDIM, 1);
        gemm_h<false, false><<<gh_grid(Mtok, 3 * CDIM), 256, GSMEM>>>(
            Mtok, 3 * CDIM, CDIM, h16, w_qkv + (size_t)i * CDIM * 3 * CDIM,
            nullptr, nullptr, qkv);
        flash_kernel<<<dim3((NTOK + FBQ - 1) / FBQ, NHEADS, BATCH), 256>>>();
        gemm_h<false, false><<<gh_grid(Mtok, CDIM), 256, GSMEM>>>(
            Mtok, CDIM, CDIM, o16, w_proj + (size_t)i * CDIM * CDIM,
            proj_b + i * CDIM, t, t);
        ln_kernel<<<Mtok, 256>>>(t, CDIM, ln2_w + i * CDIM, ln2_b + i * CDIM,
                                 h16, CDIM, 1);
        gemm_h<true, true><<<gh_grid(Mtok, HIDDIM), 256, GSMEM>>>(
            Mtok, HIDDIM, CDIM, h16, w_mlp1 + (size_t)i * CDIM * HIDDIM,
            mlp_b1 + i * HIDDIM, nullptr, mlp16);
        gemm_h<false, false><<<gh_grid(Mtok, CDIM), 256, GSMEM>>>(
            Mtok, CDIM, HIDDIM, mlp16, w_mlp2 + (size_t)i * HIDDIM * CDIM,
            mlp_b2 + i * CDIM, t, t);
    }

    ln_kernel<<<BATCH, 256>>>(t, (long)NTOK * CDIM, norm_w, norm_b, cls, CDIM, 0);
    gemm_small<<<dim3((NCLS + BN - 1) / BN, 1), 256>>>(
        BATCH, NCLS, CDIM, cls, head_w, head_b, out);
}

// round 12
// speedup vs baseline: 1.6399x; 1.0472x over previous
#include <cuda_runtime.h>
#include <cuda_fp16.h>
#include <math.h>
#include <stdint.h>

#define BATCH 32
#define DEPTH 12
#define CDIM 768
#define NHEADS 12
#define HD 64
#define NTOK 197
#define NPATCH 196
#define GRD 14
#define PSZ 16
#define HIDDIM 3072
#define NCLS 1000
#define IMG 224
#define HALFW 3

// ---------------- scratch (device globals; no allocation allowed) -------------
__device__ __half g_xp16[BATCH * NPATCH * CDIM];
__device__ __half g_h16[BATCH * NTOK * CDIM];
__device__ __half g_o16[BATCH * NTOK * CDIM];
__device__ __half g_mlp16[BATCH * NTOK * HIDDIM];
__device__ float g_t[BATCH * NTOK * CDIM];
__device__ float g_h[BATCH * NTOK * CDIM];
__device__ float g_qkv[BATCH * NTOK * 3 * CDIM];
__device__ float g_cls[BATCH * CDIM];

// weights: (N,K) layout, fp16
#define W_PATCH_SZ (CDIM * 3 * PSZ * PSZ)
#define W_QKV_SZ   (DEPTH * CDIM * 3 * CDIM)
#define W_PROJ_SZ  (DEPTH * CDIM * CDIM)
#define W_MLP1_SZ  (DEPTH * CDIM * HIDDIM)
#define W_MLP2_SZ  (DEPTH * HIDDIM * CDIM)
#define OFF_PATCH 0
#define OFF_QKV   (OFF_PATCH + W_PATCH_SZ)
#define OFF_PROJ  (OFF_QKV + W_QKV_SZ)
#define OFF_MLP1  (OFF_PROJ + W_PROJ_SZ)
#define OFF_MLP2  (OFF_MLP1 + W_MLP1_SZ)
#define W_TOTAL   (OFF_MLP2 + W_MLP2_SZ)
__device__ __half g_w16[W_TOTAL];

// ---------------- helpers ------------------------------------------------------
__device__ __forceinline__ uint32_t smem_u32(const void* p) {
    uint32_t a;
    asm("{ .reg .u64 t; cvta.to.shared.u64 t, %1; cvt.u32.u64 %0, t; }"
        : "=r"(a) : "l"(p));
    return a;
}
__device__ __forceinline__ void cp16(uint32_t dst_smem, const void* src, int size) {
    asm volatile("cp.async.cg.shared.global [%0], [%1], 16, %2;\n"
                 :: "r"(dst_smem), "l"(src), "r"(size));
}
__device__ __forceinline__ void cp_commit() {
    asm volatile("cp.async.commit_group;\n");
}
template <int NWAIT>
__device__ __forceinline__ void cp_wait() {
    asm volatile("cp.async.wait_group %0;\n" :: "n"(NWAIT));
}

__device__ __forceinline__ void mma_f16(float* d, const uint32_t* a, const uint32_t* b) {
    asm volatile(
        "mma.sync.aligned.m16n8k16.row.col.f32.f16.f16.f32 "
        "{%0,%1,%2,%3}, {%4,%5,%6,%7}, {%8,%9}, {%0,%1,%2,%3};"
        : "+f"(d[0]), "+f"(d[1]), "+f"(d[2]), "+f"(d[3])
        : "r"(a[0]), "r"(a[1]), "r"(a[2]), "r"(a[3]), "r"(b[0]), "r"(b[1]));
}

__device__ __forceinline__ void ldsm_x4(uint32_t& r0, uint32_t& r1,
                                        uint32_t& r2, uint32_t& r3, uint32_t addr) {
    asm volatile("ldmatrix.sync.aligned.m8n8.x4.shared.b16 {%0,%1,%2,%3}, [%4];"
                 : "=r"(r0), "=r"(r1), "=r"(r2), "=r"(r3) : "r"(addr));
}

// ================= FP16 tensor-core GEMM, cp.async 3-stage + ldmatrix =========
// C(MxN) = A(MxK) @ Bw(N,K)^T, A/Bw fp16, accumulate fp32.
// Block 128x128, 8 warps (warp tile 64x32 = 4x4 m16n8k16 frags), K slab 32.
#define GM 128
#define GN 128
#define GKH 32
#define ROWB 80                 // padded smem row: 64B data + 16B pad
#define ROWH 40                 // row stride in halves
#define TILEB (GM * ROWB)       // 10240
#define STAGEB (2 * TILEB)      // 20480
#define NST 3
#define GSMEM (NST * STAGEB)    // 61440

template <bool GELU, bool OUTH>
__global__ void __launch_bounds__(256, 2)
gemm_h(int M, int N, int K,
       const __half* __restrict__ A, const __half* __restrict__ Bw,
       const float* __restrict__ bias, const float* __restrict__ resid,
       void* __restrict__ Cout) {
    extern __shared__ char dsm[];
    const uint32_t sb = smem_u32(dsm);
    const int tid = threadIdx.x;
    const int lane = tid & 31;
    const int warp = tid >> 5;
    const int m0 = blockIdx.y * GM;
    const int n0 = blockIdx.x * GN;
    const int wm = (warp >> 2) * 64;
    const int wn = (warp & 3) * 32;
    const int r = lane >> 2;
    const int c = lane & 3;

    // ldmatrix per-lane address components
    const int l8 = lane & 7;          // row within 8x8 tile
    const int lq = lane >> 3;         // which of the 4 matrices (0..3)

    float acc[4][4][4];
#pragma unroll
    for (int mt = 0; mt < 4; mt++)
#pragma unroll
        for (int nt = 0; nt < 4; nt++)
#pragma unroll
            for (int i = 0; i < 4; i++) acc[mt][nt][i] = 0.f;

    const int iters = K / GKH;

    auto load_stage = [&](int s, int k0) {
        const uint32_t aB = sb + s * STAGEB;
        const uint32_t bB = aB + TILEB;
#pragma unroll
        for (int j = 0; j < 2; j++) {
            int ci = tid + j * 256;
            int row = ci >> 2, ch = ci & 3;
            int gm = m0 + row;
            cp16(aB + row * ROWB + ch * 16,
                 &A[(size_t)gm * K + k0 + ch * 8], (gm < M) ? 16 : 0);
            cp16(bB + row * ROWB + ch * 16,
                 &Bw[(size_t)(n0 + row) * K + k0 + ch * 8], 16);
        }
    };

    load_stage(0, 0);
    cp_commit();
    load_stage(1, GKH);
    cp_commit();

    int buf = 0;
    for (int it = 0; it < iters; ++it) {
        cp_wait<1>();
        __syncthreads();

        const uint32_t aS = sb + buf * STAGEB;
        const uint32_t bS = aS + TILEB;

#pragma unroll
        for (int ks = 0; ks < GKH; ks += 16) {
            uint32_t af[4][4], bf[4][2];
            // A: one ldmatrix.x4 per 16x16 mt tile.
            // matrices: 0=(m0-7,k0-7) 1=(m8-15,k0-7) 2=(m0-7,k8-15) 3=(m8-15,k8-15)
#pragma unroll
            for (int mt = 0; mt < 4; mt++) {
                int arow = wm + mt * 16 + l8 + ((lq & 1) << 3);
                int acolb = (ks + ((lq >> 1) << 3)) * 2;
                ldsm_x4(af[mt][0], af[mt][1], af[mt][2], af[mt][3],
                        aS + arow * ROWB + acolb);
            }
            // B: two ldmatrix.x4, each covering 2 nt tiles x 2 k-halves.
            // op0 matrices: 0=(n0-7,k0) 1=(n0-7,k8) 2=(n8-15,k0) 3=(n8-15,k8)
            {
                int brow = wn + ((lq >> 1) << 3) + l8;
                int bcolb = (ks + ((lq & 1) << 3)) * 2;
                ldsm_x4(bf[0][0], bf[0][1], bf[1][0], bf[1][1],
                        bS + brow * ROWB + bcolb);
                ldsm_x4(bf[2][0], bf[2][1], bf[3][0], bf[3][1],
                        bS + (brow + 16) * ROWB + bcolb);
            }
#pragma unroll
            for (int mt = 0; mt < 4; mt++)
#pragma unroll
                for (int nt = 0; nt < 4; nt++)
                    mma_f16(acc[mt][nt], af[mt], bf[nt]);
        }
        __syncthreads();

        if (it + 2 < iters) {
            int nb2 = buf + 2;
            if (nb2 >= NST) nb2 -= NST;
            load_stage(nb2, (it + 2) * GKH);
        }
        cp_commit();

        buf = (buf == NST - 1) ? 0 : buf + 1;
    }

    // ---- epilogue ----
#pragma unroll
    for (int mt = 0; mt < 4; mt++) {
#pragma unroll
        for (int half = 0; half < 2; half++) {
            int gm = m0 + wm + mt * 16 + r + half * 8;
            if (gm >= M) continue;
#pragma unroll
            for (int nt = 0; nt < 4; nt++) {
                int gn = n0 + wn + nt * 8 + c * 2;
                float v0 = acc[mt][nt][half * 2 + 0];
                float v1 = acc[mt][nt][half * 2 + 1];
                if (bias) {
                    v0 += bias[gn];
                    v1 += bias[gn + 1];
                }
                if (GELU) {
                    v0 = 0.5f * v0 * (1.f + erff(v0 * 0.70710678118654752f));
                    v1 = 0.5f * v1 * (1.f + erff(v1 * 0.70710678118654752f));
                }
                if (resid) {
                    const float2 rr = *reinterpret_cast<const float2*>(
                        &resid[(size_t)gm * N + gn]);
                    v0 += rr.x;
                    v1 += rr.y;
                }
                if (OUTH) {
                    __half2 hv = __floats2half2_rn(v0, v1);
                    *reinterpret_cast<__half2*>(
                        (__half*)Cout + (size_t)gm * N + gn) = hv;
                } else {
                    *reinterpret_cast<float2*>(
                        (float*)Cout + (size_t)gm * N + gn) = make_float2(v0, v1);
                }
            }
        }
    }
}

// ---------------- weight preprocessing ----------------------------------------
// convert-only: src already (N,K) fp32 -> fp16
__global__ void half_kernel(const float* __restrict__ src, __half* __restrict__ dst,
                            int n4) {
    int i = blockIdx.x * blockDim.x + threadIdx.x;
    if (i >= n4) return;
    float4 v = reinterpret_cast<const float4*>(src)[i];
    __half2 h0 = __floats2half2_rn(v.x, v.y);
    __half2 h1 = __floats2half2_rn(v.z, v.w);
    reinterpret_cast<__half2*>(dst)[2 * i + 0] = h0;
    reinterpret_cast<__half2*>(dst)[2 * i + 1] = h1;
}

// (K,N) fp32 row-major -> (N,K) fp16 row-major; layer via blockIdx.z
__global__ void __launch_bounds__(256)
transpose_half_kernel(const float* __restrict__ src, __half* __restrict__ dst,
                      int K, int N) {
    __shared__ float tile[32][33];
    const float* s = src + (size_t)blockIdx.z * K * N;
    __half* d = dst + (size_t)blockIdx.z * K * N;
    int kb = blockIdx.y * 32, nb = blockIdx.x * 32;
    int tx = threadIdx.x & 31, ty = threadIdx.x >> 5;
#pragma unroll
    for (int r = 0; r < 32; r += 8)
        tile[ty + r][tx] = s[(size_t)(kb + ty + r) * N + nb + tx];
    __syncthreads();
#pragma unroll
    for (int r = 0; r < 32; r += 8)
        d[(size_t)(nb + ty + r) * K + kb + tx] = __float2half(tile[tx][ty + r]);
}

// ---------------- small SIMT GEMM (head: M=32, N=1000) ------------------------
#define BN 128

__global__ void __launch_bounds__(256)
gemm_small(int M, int N, int K,
           const float* __restrict__ A, const float* __restrict__ B,
           const float* __restrict__ bias, float* __restrict__ C) {
    __shared__ float As[8][128];
    __shared__ float Bs[8][132];
    const int tid = threadIdx.x;
    const int m0 = blockIdx.y * 128;
    const int n0 = blockIdx.x * BN;
    const int tx = tid % 16;
    const int ty = tid / 16;

    float acc[8][8];
#pragma unroll
    for (int i = 0; i < 8; i++)
#pragma unroll
        for (int j = 0; j < 8; j++) acc[i][j] = 0.f;

    const int arow = tid / 2;
    const int acol = (tid % 2) * 4;
    const int brow = tid / 32;
    const int bcol = (tid % 32) * 4;

    for (int k0 = 0; k0 < K; k0 += 8) {
        {
            int gm = m0 + arow;
            float4 v = make_float4(0.f, 0.f, 0.f, 0.f);
            if (gm < M)
                v = *reinterpret_cast<const float4*>(&A[(size_t)gm * K + k0 + acol]);
            As[acol + 0][arow] = v.x;
            As[acol + 1][arow] = v.y;
            As[acol + 2][arow] = v.z;
            As[acol + 3][arow] = v.w;
        }
        {
            int gn = n0 + bcol;
            Bs[brow][bcol + 0] = (gn + 0 < N) ? B[(size_t)(k0 + brow) * N + gn + 0] : 0.f;
            Bs[brow][bcol + 1] = (gn + 1 < N) ? B[(size_t)(k0 + brow) * N + gn + 1] : 0.f;
            Bs[brow][bcol + 2] = (gn + 2 < N) ? B[(size_t)(k0 + brow) * N + gn + 2] : 0.f;
            Bs[brow][bcol + 3] = (gn + 3 < N) ? B[(size_t)(k0 + brow) * N + gn + 3] : 0.f;
        }
        __syncthreads();
#pragma unroll
        for (int kk = 0; kk < 8; kk++) {
            float ra[8], rb[8];
#pragma unroll
            for (int i = 0; i < 8; i++) ra[i] = As[kk][ty * 8 + i];
#pragma unroll
            for (int j = 0; j < 8; j++) rb[j] = Bs[kk][tx * 8 + j];
#pragma unroll
            for (int i = 0; i < 8; i++)
#pragma unroll
                for (int j = 0; j < 8; j++) acc[i][j] = fmaf(ra[i], rb[j], acc[i][j]);
        }
        __syncthreads();
    }
#pragma unroll
    for (int i = 0; i < 8; i++) {
        int gm = m0 + ty * 8 + i;
        if (gm >= M) continue;
#pragma unroll
        for (int j = 0; j < 8; j++) {
            int gn = n0 + tx * 8 + j;
            if (gn >= N) continue;
            float v = acc[i][j];
            if (bias) v += bias[gn];
            C[(size_t)gm * N + gn] = v;
        }
    }
}

// ---------------- patch gather (fp16 output) ----------------------------------
__global__ void gather_kernel(const float* __restrict__ x) {
    int idx = blockIdx.x * blockDim.x + threadIdx.x;
    const int total = BATCH * NPATCH * CDIM;
    if (idx >= total) return;
    int k = idx % CDIM;
    int g = (idx / CDIM) % NPATCH;
    int b = idx / (CDIM * NPATCH);
    int ch = k / (PSZ * PSZ);
    int pr = (k / PSZ) % PSZ;
    int pc = k % PSZ;
    int gr = g / GRD;
    int gc = g % GRD;
    g_xp16[idx] = __float2half(
        x[(((size_t)b * 3 + ch) * IMG + gr * PSZ + pr) * IMG + gc * PSZ + pc]);
}

// ---------------- assemble t = [cls; patches] + pos --------------------------
__global__ void assemble_kernel(const float* __restrict__ cls_tok,
                                const float* __restrict__ pos) {
    int idx = blockIdx.x * blockDim.x + threadIdx.x;
    const int total = BATCH * NTOK * CDIM;
    if (idx >= total) return;
    int c = idx % CDIM;
    int n = (idx / CDIM) % NTOK;
    int b = idx / (CDIM * NTOK);
    float v = (n == 0) ? cls_tok[c] : g_h[((size_t)b * NPATCH + n - 1) * CDIM + c];
    g_t[idx] = v + pos[(size_t)n * CDIM + c];
}

// ---------------- layernorm (warp-shuffle; half or float out) -----------------
__global__ void __launch_bounds__(256)
ln_kernel(const float* __restrict__ x, long in_stride,
          const float* __restrict__ w, const float* __restrict__ b,
          void* __restrict__ y, long out_stride, int half_out) {
    const float* row = x + (size_t)blockIdx.x * in_stride;
    int tid = threadIdx.x;
    float v0 = row[tid], v1 = row[tid + 256], v2 = row[tid + 512];
    float s = v0 + v1 + v2;
    float s2 = v0 * v0 + v1 * v1 + v2 * v2;
#pragma unroll
    for (int o = 16; o > 0; o >>= 1) {
        s += __shfl_xor_sync(0xffffffffu, s, o);
        s2 += __shfl_xor_sync(0xffffffffu, s2, o);
    }
    __shared__ float ps[8], ps2[8];
    if ((tid & 31) == 0) {
        ps[tid >> 5] = s;
        ps2[tid >> 5] = s2;
    }
    __syncthreads();
    float ts = ps[tid & 7], ts2 = ps2[tid & 7];
#pragma unroll
    for (int o = 4; o > 0; o >>= 1) {
        ts += __shfl_xor_sync(0xffffffffu, ts, o);
        ts2 += __shfl_xor_sync(0xffffffffu, ts2, o);
    }
    float mu = ts * (1.f / CDIM);
    float var = ts2 * (1.f / CDIM) - mu * mu;
    float rstd = rsqrtf(var + 1e-5f);
    float o0 = (v0 - mu) * rstd * w[tid] + b[tid];
    float o1 = (v1 - mu) * rstd * w[tid + 256] + b[tid + 256];
    float o2 = (v2 - mu) * rstd * w[tid + 512] + b[tid + 512];
    if (half_out) {
        __half* out = (__half*)y + (size_t)blockIdx.x * out_stride;
        out[tid] = __float2half(o0);
        out[tid + 256] = __float2half(o1);
        out[tid + 512] = __float2half(o2);
    } else {
        float* out = (float*)y + (size_t)blockIdx.x * out_stride;
        out[tid] = o0;
        out[tid + 256] = o1;
        out[tid + 512] = o2;
    }
}

// ---------------- fused flash attention (fp16 output) -------------------------
#define FBQ 32
#define FBK 32

__device__ __forceinline__ bool attn_allowed(int q, int k) {
    if (q == 0 || k == 0) return true;
    int qr = (q - 1) / GRD, qc = (q - 1) % GRD;
    int kr = (k - 1) / GRD, kc = (k - 1) % GRD;
    return (abs(qr - kr) <= HALFW) && (abs(qc - kc) <= HALFW);
}

__global__ void __launch_bounds__(256)
flash_kernel() {
    const int b = blockIdx.z;
    const int h = blockIdx.y;
    const int q0 = blockIdx.x * FBQ;
    const int tid = threadIdx.x;

    __shared__ float Qs[FBQ][HD + 1];
    __shared__ float Ks[FBK][HD + 1];
    __shared__ float Vs[FBK][HD + 1];
    __shared__ float Ps[FBQ][FBK + 1];

    const float* qkv = g_qkv;
    const size_t rowstride = 3 * CDIM;

    for (int idx = tid; idx < FBQ * HD; idx += 256) {
        int q = idx >> 6, d = idx & 63;
        int gq = q0 + q;
        Qs[q][d] = (gq < NTOK)
            ? qkv[((size_t)(b * NTOK + gq)) * rowstride + h * HD + d] : 0.f;
    }

    int klo = 0, khi = NTOK - 1;
    bool full = (q0 == 0);
    if (!full) {
        int qlo = q0, qhi = min(q0 + FBQ - 1, NTOK - 1);
        int qr_min = (qlo - 1) / GRD, qr_max = (qhi - 1) / GRD;
        klo = 1 + max(0, qr_min - HALFW) * GRD;
        khi = min(NTOK - 1, (qr_max + HALFW) * GRD + GRD);
    }

    const int q = tid >> 3;
    const int j = tid & 7;
    const int gq = q0 + q;
    const bool qvalid = (gq < NTOK);
    const int dbase = j * 8;

    float m_old = -INFINITY, l = 0.f;
    float acc[8];
#pragma unroll
    for (int i = 0; i < 8; i++) acc[i] = 0.f;

    for (int kt = 0; kt < (NTOK + FBK - 1) / FBK; kt++) {
        int kbase = kt * FBK;
        if (!(kt == 0 || full || (kbase + FBK - 1 >= klo && kbase <= khi)))
            continue;

        __syncthreads();
        for (int idx = tid; idx < FBK * HD; idx += 256) {
            int kk = idx >> 6, d = idx & 63;
            int gk = kbase + kk;
            if (gk < NTOK) {
                Ks[kk][d] = qkv[((size_t)(b * NTOK + gk)) * rowstride + CDIM + h * HD + d];
                Vs[kk][d] = qkv[((size_t)(b * NTOK + gk)) * rowstride + 2 * CDIM + h * HD + d];
            } else {
                Ks[kk][d] = 0.f;
                Vs[kk][d] = 0.f;
            }
        }
        __syncthreads();

        float s[4];
#pragma unroll
        for (int i = 0; i < 4; i++) {
            int kc = j + i * 8;
            float a = 0.f;
#pragma unroll
            for (int d = 0; d < HD; d++) a = fmaf(Qs[q][d], Ks[kc][d], a);
            a *= 0.125f;
            int gk = kbase + kc;
            if (!qvalid || gk >= NTOK || !attn_allowed(gq, gk)) a = -INFINITY;
            s[i] = a;
        }
        float mt = fmaxf(fmaxf(s[0], s[1]), fmaxf(s[2], s[3]));
#pragma unroll
        for (int o = 1; o < 8; o <<= 1)
            mt = fmaxf(mt, __shfl_xor_sync(0xffffffffu, mt, o));
        float m_new = fmaxf(m_old, mt);
        float scale = (m_new == -INFINITY) ? 1.f : __expf(m_old - m_new);
        float psum = 0.f;
#pragma unroll
        for (int i = 0; i < 4; i++) {
            float p = (s[i] == -INFINITY) ? 0.f : __expf(s[i] - m_new);
            Ps[q][j + i * 8] = p;
            psum += p;
        }
#pragma unroll
        for (int o = 1; o < 8; o <<= 1)
            psum += __shfl_xor_sync(0xffffffffu, psum, o);
        l = l * scale + psum;
        m_old = m_new;
        __syncwarp();

#pragma unroll
        for (int i = 0; i < 8; i++) acc[i] *= scale;
        for (int kk = 0; kk < FBK; kk++) {
            float p = Ps[q][kk];
#pragma unroll
            for (int i = 0; i < 8; i++)
                acc[i] = fmaf(p, Vs[kk][dbase + i], acc[i]);
        }
        __syncwarp();
    }

    if (qvalid) {
        float inv = 1.f / l;
#pragma unroll
        for (int i = 0; i < 8; i++)
            g_o16[((size_t)(b * NTOK + gq)) * CDIM + h * HD + dbase + i] =
                __float2half(acc[i] * inv);
    }
}

// ---------------- launch helpers ---------------------------------------------
static inline dim3 gh_grid(int M, int N) {
    return dim3(N / GN, (M + GM - 1) / GM);
}

extern "C" void kernel_launch(void* const* d_in, const int* in_sizes, int n_in,
                              void* d_out, int out_size) {
    const float* x       = (const float*)d_in[0];
    const float* patch_w = (const float*)d_in[1];
    const float* patch_b = (const float*)d_in[2];
    const float* cls_tok = (const float*)d_in[3];
    const float* pos     = (const float*)d_in[4];
    const float* ln1_w   = (const float*)d_in[5];
    const float* ln1_b   = (const float*)d_in[6];
    const float* qkv_w   = (const float*)d_in[7];
    const float* proj_w  = (const float*)d_in[8];
    const float* proj_b  = (const float*)d_in[9];
    const float* ln2_w   = (const float*)d_in[10];
    const float* ln2_b   = (const float*)d_in[11];
    const float* mlp_w1  = (const float*)d_in[12];
    const float* mlp_b1  = (const float*)d_in[13];
    const float* mlp_w2  = (const float*)d_in[14];
    const float* mlp_b2  = (const float*)d_in[15];
    const float* norm_w  = (const float*)d_in[16];
    const float* norm_b  = (const float*)d_in[17];
    const float* head_w  = (const float*)d_in[18];
    const float* head_b  = (const float*)d_in[19];
    float* out = (float*)d_out;

    float *t, *h, *qkv, *cls;
    __half *xp16, *h16, *o16, *mlp16, *w16;
    cudaGetSymbolAddress((void**)&t, g_t);
    cudaGetSymbolAddress((void**)&h, g_h);
    cudaGetSymbolAddress((void**)&qkv, g_qkv);
    cudaGetSymbolAddress((void**)&cls, g_cls);
    cudaGetSymbolAddress((void**)&xp16, g_xp16);
    cudaGetSymbolAddress((void**)&h16, g_h16);
    cudaGetSymbolAddress((void**)&o16, g_o16);
    cudaGetSymbolAddress((void**)&mlp16, g_mlp16);
    cudaGetSymbolAddress((void**)&w16, g_w16);

    cudaFuncSetAttribute(gemm_h<false, false>,
                         cudaFuncAttributeMaxDynamicSharedMemorySize, GSMEM);
    cudaFuncSetAttribute(gemm_h<true, true>,
                         cudaFuncAttributeMaxDynamicSharedMemorySize, GSMEM);

    const __half* w_patch = w16 + OFF_PATCH;
    const __half* w_qkv   = w16 + OFF_QKV;
    const __half* w_proj  = w16 + OFF_PROJ;
    const __half* w_mlp1  = w16 + OFF_MLP1;
    const __half* w_mlp2  = w16 + OFF_MLP2;

    // ---- preprocess weights: (N,K) fp16 ----
    half_kernel<<<(W_PATCH_SZ / 4 + 255) / 256, 256>>>(
        patch_w, w16 + OFF_PATCH, W_PATCH_SZ / 4);  // already (N,K)
    transpose_half_kernel<<<dim3(3 * CDIM / 32, CDIM / 32, DEPTH), 256>>>(
        qkv_w, w16 + OFF_QKV, CDIM, 3 * CDIM);
    transpose_half_kernel<<<dim3(CDIM / 32, CDIM / 32, DEPTH), 256>>>(
        proj_w, w16 + OFF_PROJ, CDIM, CDIM);
    transpose_half_kernel<<<dim3(HIDDIM / 32, CDIM / 32, DEPTH), 256>>>(
        mlp_w1, w16 + OFF_MLP1, CDIM, HIDDIM);
    transpose_half_kernel<<<dim3(CDIM / 32, HIDDIM / 32, DEPTH), 256>>>(
        mlp_w2, w16 + OFF_MLP2, HIDDIM, CDIM);

    const int Mtok = BATCH * NTOK;  // 6304

    // patch embed
    {
        int total = BATCH * NPATCH * CDIM;
        gather_kernel<<<(total + 255) / 256, 256>>>(x);
        gemm_h<false, false><<<gh_grid(BATCH * NPATCH, CDIM), 256, GSMEM>>>(
            BATCH * NPATCH, CDIM, CDIM, xp16, w_patch, patch_b, nullptr, h);
        int tot2 = BATCH * NTOK * CDIM;
        assemble_kernel<<<(tot2 + 255) / 256, 256>>>(cls_tok, pos);
    }

    for (int i = 0; i < DEPTH; i++) {
        ln_kernel<<<Mtok, 256>>>(t, CDIM, ln1_w + i * CDIM, ln1_b + i * CDIM,
                                 h16, CDIM, 1);
        gemm_h<false, false><<<gh_grid(Mtok, 3 * CDIM), 256, GSMEM>>>(
            Mtok, 3 * CDIM, CDIM, h16, w_qkv + (size_t)i * CDIM * 3 * CDIM,
            nullptr, nullptr, qkv);
        flash_kernel<<<dim3((NTOK + FBQ - 1) / FBQ, NHEADS, BATCH), 256>>>();
        gemm_h<false, false><<<gh_grid(Mtok, CDIM), 256, GSMEM>>>(
            Mtok, CDIM, CDIM, o16, w_proj + (size_t)i * CDIM * CDIM,
            proj_b + i * CDIM, t, t);
        ln_kernel<<<Mtok, 256>>>(t, CDIM, ln2_w + i * CDIM, ln2_b + i * CDIM,
                                 h16, CDIM, 1);
        gemm_h<true, true><<<gh_grid(Mtok, HIDDIM), 256, GSMEM>>>(
            Mtok, HIDDIM, CDIM, h16, w_mlp1 + (size_t)i * CDIM * HIDDIM,
            mlp_b1 + i * HIDDIM, nullptr, mlp16);
        gemm_h<false, false><<<gh_grid(Mtok, CDIM), 256, GSMEM>>>(
            Mtok, CDIM, HIDDIM, mlp16, w_mlp2 + (size_t)i * HIDDIM * CDIM,
            mlp_b2 + i * CDIM, t, t);
    }

    ln_kernel<<<BATCH, 256>>>(t, (long)NTOK * CDIM, norm_w, norm_b, cls, CDIM, 0);
    gemm_small<<<dim3((NCLS + BN - 1) / BN, 1), 256>>>(
        BATCH, NCLS, CDIM, cls, head_w, head_b, out);
}